// round 4
// baseline (speedup 1.0000x reference)
#include <cuda_runtime.h>
#include <math.h>
#include <float.h>
#include <stdint.h>

// Problem constants
#define B_   8
#define E_   256
#define N_   32
#define D_   512
#define RD_  768
#define R_   2000
#define L_   2
#define K_   8
#define M_   32
#define H_   8
#define DH_  64
#define HL_  4096
#define BE_  (B_*E_)     // 2048
#define FF_  (4*D_)      // 2048

// ---------------- scratch (device globals; no allocation allowed) ----------------
__device__ float g_proj [R_*D_];      // projected relation table  [2000,512]
__device__ float g_invn [R_];         // 1/max(norm,1e-12) per relation
__device__ float g_agg  [BE_*D_];     // top-k aggregated context  [2048,512]
__device__ float g_states[BE_*D_];    // edge states               [2048,512]
__device__ float g_t1   [BE_*D_];
__device__ float g_t2   [BE_*D_];
__device__ float g_hid  [BE_*FF_];    // FFN hidden [2048,2048]
__device__ float g_kbuf [BE_*D_];
__device__ float g_vbuf [BE_*D_];
__device__ float g_qbuf [M_*D_];
__device__ float g_mem  [B_*M_*D_];
__device__ float g_memo [B_*M_*D_];
__device__ float g_flag [B_];

// ---------------- reductions ----------------
__device__ __forceinline__ float warpSum(float v) {
    #pragma unroll
    for (int o = 16; o; o >>= 1) v += __shfl_down_sync(0xFFFFFFFFu, v, o);
    return v;
}
__device__ __forceinline__ float warpMax(float v) {
    #pragma unroll
    for (int o = 16; o; o >>= 1) v = fmaxf(v, __shfl_down_sync(0xFFFFFFFFu, v, o));
    return v;
}
// 256-thread block sum with broadcast
__device__ __forceinline__ float blockSum256(float v, float* red) {
    float w = warpSum(v);
    if ((threadIdx.x & 31) == 0) red[threadIdx.x >> 5] = w;
    __syncthreads();
    float s = 0.f;
    #pragma unroll
    for (int i = 0; i < 8; i++) s += red[i];
    __syncthreads();
    return s;
}
__device__ __forceinline__ float blockMax256(float v, float* red) {
    float w = warpMax(v);
    if ((threadIdx.x & 31) == 0) red[threadIdx.x >> 5] = w;
    __syncthreads();
    float s = -FLT_MAX;
    #pragma unroll
    for (int i = 0; i < 8; i++) s = fmaxf(s, red[i]);
    __syncthreads();
    return s;
}

// ---------------- generic tiled SGEMM: C[M,N] = A[M,K] @ W[N,K]^T + bias ----------------
// EPI: 0 = none, 1 = exact GELU, 2 = multiply by flag[row/flagdiv]
template<int EPI>
__global__ void gemm_kernel(const float* __restrict__ A, const float* __restrict__ W,
                            const float* __restrict__ bias, float* __restrict__ C,
                            int M, int N, int K, const float* __restrict__ flag, int flagdiv)
{
    __shared__ float As[16][68];   // [k][m], stride 68 floats (16B-aligned rows)
    __shared__ float Bs[16][68];   // [k][n]
    const int bm = blockIdx.y * 64, bn = blockIdx.x * 64;
    const int tid = threadIdx.x;
    const int ty = tid >> 4, tx = tid & 15;
    float acc[4][4] = {};

    for (int k0 = 0; k0 < K; k0 += 16) {
        #pragma unroll
        for (int j = 0; j < 4; j++) {
            int idx = tid + j * 256;           // 0..1023
            int m  = idx >> 4;                 // 0..63
            int kk = idx & 15;                 // 0..15
            int gm = bm + m;
            As[kk][m] = (gm < M) ? A[(size_t)gm * K + k0 + kk] : 0.f;
            int gn = bn + m;
            Bs[kk][m] = (gn < N) ? W[(size_t)gn * K + k0 + kk] : 0.f;
        }
        __syncthreads();
        #pragma unroll
        for (int kk = 0; kk < 16; kk++) {
            float a[4], b[4];
            const float4 av = *reinterpret_cast<const float4*>(&As[kk][ty * 4]);
            const float4 bv = *reinterpret_cast<const float4*>(&Bs[kk][tx * 4]);
            a[0]=av.x; a[1]=av.y; a[2]=av.z; a[3]=av.w;
            b[0]=bv.x; b[1]=bv.y; b[2]=bv.z; b[3]=bv.w;
            #pragma unroll
            for (int i = 0; i < 4; i++)
                #pragma unroll
                for (int j = 0; j < 4; j++) acc[i][j] += a[i] * b[j];
        }
        __syncthreads();
    }

    #pragma unroll
    for (int i = 0; i < 4; i++) {
        int gm = bm + ty * 4 + i;
        if (gm >= M) continue;
        float fl = 1.f;
        if (EPI == 2) fl = flag[gm / flagdiv];
        #pragma unroll
        for (int j = 0; j < 4; j++) {
            int gn = bn + tx * 4 + j;
            if (gn >= N) continue;
            float v = acc[i][j] + bias[gn];
            if (EPI == 1) v = 0.5f * v * (1.f + erff(v * 0.70710678118654752440f));
            if (EPI == 2) v *= fl;
            C[(size_t)gm * N + gn] = v;
        }
    }
}

// ---------------- inverse norm per relation ----------------
__global__ void invnorm_kernel() {
    const int r = blockIdx.x;
    __shared__ float red[4];
    float s = 0.f;
    for (int d = threadIdx.x; d < D_; d += 128) {
        float x = g_proj[(size_t)r * D_ + d];
        s += x * x;
    }
    s = warpSum(s);
    if ((threadIdx.x & 31) == 0) red[threadIdx.x >> 5] = s;
    __syncthreads();
    if (threadIdx.x == 0) {
        float t = red[0] + red[1] + red[2] + red[3];
        g_invn[r] = 1.f / fmaxf(sqrtf(t), 1e-12f);
    }
}

// ---------------- per-edge: sims, top-k, agg, init states ----------------
__global__ void sims_kernel(const int* __restrict__ eids, const int* __restrict__ nids) {
    const int row = blockIdx.x;               // b*E + e
    __shared__ float rv[D_];
    __shared__ float sims[N_];
    __shared__ int   nid_s[N_];
    __shared__ int   sel[K_];
    const int eid = eids[row];
    for (int d = threadIdx.x; d < D_; d += 256) rv[d] = g_proj[(size_t)eid * D_ + d];
    if (threadIdx.x < N_) nid_s[threadIdx.x] = nids[(size_t)row * N_ + threadIdx.x];
    __syncthreads();

    const int g = threadIdx.x >> 3, sub = threadIdx.x & 7;   // 32 groups x 8 threads
    const int nid = nid_s[g];
    const float* np = &g_proj[(size_t)nid * D_];
    float acc = 0.f;
    for (int d = sub; d < D_; d += 8) acc += np[d] * rv[d];
    acc += __shfl_down_sync(0xFFFFFFFFu, acc, 4, 8);
    acc += __shfl_down_sync(0xFFFFFFFFu, acc, 2, 8);
    acc += __shfl_down_sync(0xFFFFFFFFu, acc, 1, 8);
    if (sub == 0) sims[g] = acc * g_invn[nid] * g_invn[eid];
    __syncthreads();

    if (threadIdx.x == 0) {       // stable top-K (lowest index wins on ties, like lax.top_k)
        unsigned used = 0;
        for (int k = 0; k < K_; k++) {
            float best = -FLT_MAX; int bi = 0;
            for (int n = 0; n < N_; n++)
                if (!((used >> n) & 1u) && sims[n] > best) { best = sims[n]; bi = n; }
            used |= 1u << bi;
            sel[k] = nid_s[bi];
        }
    }
    __syncthreads();

    for (int d = threadIdx.x; d < D_; d += 256) {
        float s = 0.f;
        #pragma unroll
        for (int k = 0; k < K_; k++) s += g_proj[(size_t)sel[k] * D_ + d];
        g_agg[(size_t)row * D_ + d]    = s * (1.f / K_);
        g_states[(size_t)row * D_ + d] = rv[d];
    }
}

// ---------------- residual add + LayerNorm (+ optional mask) ----------------
__global__ void addln_kernel(float* __restrict__ states, const float* __restrict__ delta,
                             const float* __restrict__ gam, const float* __restrict__ bet,
                             const float* __restrict__ mask, int useMask)
{
    const int row = blockIdx.x;
    __shared__ float xs[D_];
    __shared__ float red[8];
    float s = 0.f;
    #pragma unroll
    for (int i = 0; i < 2; i++) {
        int d = threadIdx.x + i * 256;
        float x = states[(size_t)row * D_ + d] + delta[(size_t)row * D_ + d];
        xs[d] = x; s += x;
    }
    s = blockSum256(s, red);
    const float mu = s * (1.f / D_);
    float v = 0.f;
    #pragma unroll
    for (int i = 0; i < 2; i++) {
        int d = threadIdx.x + i * 256;
        float t = xs[d] - mu; v += t * t;
    }
    v = blockSum256(v, red) * (1.f / D_);
    const float r = rsqrtf(v + 1e-5f);
    const float mk = useMask ? mask[row] : 1.f;
    #pragma unroll
    for (int i = 0; i < 2; i++) {
        int d = threadIdx.x + i * 256;
        states[(size_t)row * D_ + d] = ((xs[d] - mu) * r * gam[d] + bet[d]) * mk;
    }
}

// ---------------- per-batch edge-count flag ----------------
__global__ void flag_kernel(const float* __restrict__ mask) {
    const int b = blockIdx.x;
    __shared__ float red[8];
    float s = mask[b * E_ + threadIdx.x];
    s = blockSum256(s, red);
    if (threadIdx.x == 0) g_flag[b] = (s == 0.f) ? 0.f : 1.f;
}

// ---------------- memory-token cross attention ----------------
__global__ void attn_kernel(const float* __restrict__ mask) {
    const int b = blockIdx.x / M_, m = blockIdx.x % M_;
    __shared__ float qh[DH_];
    __shared__ float w[E_];
    __shared__ float red[8];
    const int tid = threadIdx.x;                    // == e (E_ == 256)
    const float scale = 0.125f;                     // 1/sqrt(64)
    const float mk = mask[b * E_ + tid];

    for (int h = 0; h < H_; h++) {
        if (tid < DH_) qh[tid] = g_qbuf[(size_t)m * D_ + h * DH_ + tid];
        __syncthreads();
        const float4* kp4 = reinterpret_cast<const float4*>(
            &g_kbuf[((size_t)(b * E_ + tid)) * D_ + h * DH_]);
        const float4* qh4 = reinterpret_cast<const float4*>(qh);
        float s = 0.f;
        #pragma unroll
        for (int d = 0; d < DH_ / 4; d++) {
            float4 kv = kp4[d], qv = qh4[d];
            s += kv.x * qv.x + kv.y * qv.y + kv.z * qv.z + kv.w * qv.w;
        }
        s *= scale;
        if (mk == 0.f) s = -FLT_MAX;
        float mx = blockMax256(s, red);
        float e  = expf(s - mx);
        float sm = blockSum256(e, red);
        w[tid] = e / sm;
        __syncthreads();
        if (tid < DH_) {
            float acc = 0.f;
            #pragma unroll 4
            for (int e2 = 0; e2 < E_; e2++)
                acc += w[e2] * g_vbuf[((size_t)(b * E_ + e2)) * D_ + h * DH_ + tid];
            g_mem[((size_t)(b * M_ + m)) * D_ + h * DH_ + tid] = acc;
        }
        __syncthreads();
    }
}

// ---------------- host side ----------------
static inline void run_gemm(int epi, const float* A, const float* W, const float* bias,
                            float* C, int M, int N, int K,
                            const float* flag = nullptr, int flagdiv = 1)
{
    dim3 grid(N / 64, (M + 63) / 64);
    dim3 blk(256);
    if (epi == 0)      gemm_kernel<0><<<grid, blk>>>(A, W, bias, C, M, N, K, flag, flagdiv);
    else if (epi == 1) gemm_kernel<1><<<grid, blk>>>(A, W, bias, C, M, N, K, flag, flagdiv);
    else               gemm_kernel<2><<<grid, blk>>>(A, W, bias, C, M, N, K, flag, flagdiv);
}

extern "C" void kernel_launch(void* const* d_in, const int* in_sizes, int n_in,
                              void* d_out, int out_size)
{
    const int*   eids  = (const int*)  d_in[0];
    const int*   nids  = (const int*)  d_in[1];
    const float* mask  = (const float*)d_in[2];
    const float* rel   = (const float*)d_in[3];
    const float* rp_w  = (const float*)d_in[4];
    const float* rp_b  = (const float*)d_in[5];
    const float* vw    = (const float*)d_in[6];
    const float* vb    = (const float*)d_in[7];
    const float* ow    = (const float*)d_in[8];
    const float* ob    = (const float*)d_in[9];
    const float* n1g   = (const float*)d_in[10];
    const float* n1b   = (const float*)d_in[11];
    const float* n2g   = (const float*)d_in[12];
    const float* n2b   = (const float*)d_in[13];
    const float* w1    = (const float*)d_in[14];
    const float* b1    = (const float*)d_in[15];
    const float* w2    = (const float*)d_in[16];
    const float* b2    = (const float*)d_in[17];
    const float* memq  = (const float*)d_in[18];
    const float* qw    = (const float*)d_in[19];
    const float* qb    = (const float*)d_in[20];
    const float* kw    = (const float*)d_in[21];
    const float* kb    = (const float*)d_in[22];
    const float* vw2   = (const float*)d_in[23];
    const float* vb2   = (const float*)d_in[24];
    const float* tow   = (const float*)d_in[25];
    const float* tob   = (const float*)d_in[26];
    const float* pw    = (const float*)d_in[27];
    const float* pb    = (const float*)d_in[28];
    float* out = (float*)d_out;

    float *p_proj, *p_agg, *p_states, *p_t1, *p_t2, *p_hid, *p_k, *p_v, *p_q, *p_mem, *p_memo, *p_flag;
    cudaGetSymbolAddress((void**)&p_proj,   g_proj);
    cudaGetSymbolAddress((void**)&p_agg,    g_agg);
    cudaGetSymbolAddress((void**)&p_states, g_states);
    cudaGetSymbolAddress((void**)&p_t1,     g_t1);
    cudaGetSymbolAddress((void**)&p_t2,     g_t2);
    cudaGetSymbolAddress((void**)&p_hid,    g_hid);
    cudaGetSymbolAddress((void**)&p_k,      g_kbuf);
    cudaGetSymbolAddress((void**)&p_v,      g_vbuf);
    cudaGetSymbolAddress((void**)&p_q,      g_qbuf);
    cudaGetSymbolAddress((void**)&p_mem,    g_mem);
    cudaGetSymbolAddress((void**)&p_memo,   g_memo);
    cudaGetSymbolAddress((void**)&p_flag,   g_flag);

    // 1) relation table: proj_rel = rel_emb @ rp_w^T + rp_b   [2000,512]
    run_gemm(0, rel, rp_w, rp_b, p_proj, R_, D_, RD_);
    // 2) per-relation inverse norms
    invnorm_kernel<<<R_, 128>>>();
    // 3) sims + top-k + agg + states init
    sims_kernel<<<BE_, 256>>>(eids, nids);

    // 4) relation-context layers
    for (int l = 0; l < L_; l++) {
        run_gemm(0, p_agg, vw + (size_t)l * D_ * D_, vb + l * D_, p_t1, BE_, D_, D_);
        run_gemm(0, p_t1,  ow + (size_t)l * D_ * D_, ob + l * D_, p_t2, BE_, D_, D_);
        addln_kernel<<<BE_, 256>>>(p_states, p_t2, n1g + l * D_, n1b + l * D_, mask, 0);
        run_gemm(1, p_states, w1 + (size_t)l * FF_ * D_, b1 + l * FF_, p_hid, BE_, FF_, D_);
        run_gemm(0, p_hid,    w2 + (size_t)l * D_ * FF_, b2 + l * D_,  p_t2,  BE_, D_, FF_);
        addln_kernel<<<BE_, 256>>>(p_states, p_t2, n2g + l * D_, n2b + l * D_, mask, 1);
    }

    // 5) tokenizer projections
    run_gemm(0, memq,     qw,  qb,  p_q, M_,  D_, D_);
    run_gemm(0, p_states, kw,  kb,  p_k, BE_, D_, D_);
    run_gemm(0, p_states, vw2, vb2, p_v, BE_, D_, D_);

    // 6) no-edge flags + cross attention
    flag_kernel<<<B_, 256>>>(mask);
    attn_kernel<<<B_ * M_, 256>>>(mask);

    // 7) memory out-proj (zeroed for no-edge rows) + final LLM projection
    run_gemm(2, p_mem,  tow, tob, p_memo, B_ * M_, D_,  D_, p_flag, M_);
    run_gemm(0, p_memo, pw,  pb,  out,    B_ * M_, HL_, D_);
}

// round 6
// speedup vs baseline: 1.1176x; 1.1176x over previous
#include <cuda_runtime.h>
#include <math.h>
#include <float.h>
#include <stdint.h>

// Problem constants
#define B_   8
#define E_   256
#define N_   32
#define D_   512
#define RD_  768
#define R_   2000
#define L_   2
#define K_   8
#define M_   32
#define H_   8
#define DH_  64
#define HL_  4096
#define BE_  (B_*E_)     // 2048
#define FF_  (4*D_)      // 2048

// ---------------- scratch (device globals; no allocation allowed) ----------------
__device__ float g_proj [R_*D_];      // projected relation table  [2000,512]
__device__ float g_invn [R_];         // 1/max(norm,1e-12) per relation
__device__ float g_agg  [BE_*D_];     // top-k aggregated context  [2048,512]
__device__ float g_states[BE_*D_];    // edge states               [2048,512]
__device__ float g_t1   [BE_*D_];
__device__ float g_t2   [BE_*D_];
__device__ float g_hid  [BE_*FF_];    // FFN hidden [2048,2048]
__device__ float g_kbuf [BE_*D_];
__device__ float g_vbuf [BE_*D_];
__device__ float g_qbuf [M_*D_];
__device__ float g_mem  [B_*M_*D_];
__device__ float g_memo [B_*M_*D_];
__device__ float g_flag [B_];

// ---------------- reductions ----------------
__device__ __forceinline__ float warpSum(float v) {
    #pragma unroll
    for (int o = 16; o; o >>= 1) v += __shfl_down_sync(0xFFFFFFFFu, v, o);
    return v;
}
__device__ __forceinline__ float warpMax(float v) {
    #pragma unroll
    for (int o = 16; o; o >>= 1) v = fmaxf(v, __shfl_down_sync(0xFFFFFFFFu, v, o));
    return v;
}
__device__ __forceinline__ float blockSum256(float v, float* red) {
    float w = warpSum(v);
    if ((threadIdx.x & 31) == 0) red[threadIdx.x >> 5] = w;
    __syncthreads();
    float s = 0.f;
    #pragma unroll
    for (int i = 0; i < 8; i++) s += red[i];
    __syncthreads();
    return s;
}
__device__ __forceinline__ float blockMax256(float v, float* red) {
    float w = warpMax(v);
    if ((threadIdx.x & 31) == 0) red[threadIdx.x >> 5] = w;
    __syncthreads();
    float s = -FLT_MAX;
    #pragma unroll
    for (int i = 0; i < 8; i++) s = fmaxf(s, red[i]);
    __syncthreads();
    return s;
}

// ================= 128x64x16 double-buffered SGEMM =================
// C[M,N] = A[M,K] @ W[N,K]^T + bias
// 256 threads, 8x4 micro-tile per thread, smem double buffer + reg prefetch.
// Requirements: N % 64 == 0, K % 16 == 0 (all call sites satisfy this).
// EPI: 0 = none, 1 = exact GELU, 2 = multiply by flag[row/flagdiv]
template<int EPI>
__global__ __launch_bounds__(256)
void gemm_kernel(const float* __restrict__ A, const float* __restrict__ W,
                 const float* __restrict__ bias, float* __restrict__ C,
                 int M, int N, int K, const float* __restrict__ flag, int flagdiv)
{
    __shared__ float As[2][16][132];   // [buf][k][m]  (132-stride: 528B rows, 16B-aligned)
    __shared__ float Bs[2][16][68];    // [buf][k][n]  (272B rows, 16B-aligned)

    const int bm = blockIdx.y * 128, bn = blockIdx.x * 64;
    const int tid = threadIdx.x;
    const int tx = tid & 15, ty = tid >> 4;

    // A-tile load mapping: thread covers row ar, k-cols [akc, akc+8)
    const int ar  = tid >> 1;            // 0..127
    const int akc = (tid & 1) * 8;       // 0 or 8
    // W-tile load mapping: thread covers row br, k-cols [bkc, bkc+4)
    const int br  = tid >> 2;            // 0..63
    const int bkc = (tid & 3) * 4;       // 0,4,8,12

    const bool aValid = (bm + ar) < M;
    const float* __restrict__ aPtr = A + (size_t)(bm + ar) * K + akc;
    const float* __restrict__ bPtr = W + (size_t)(bn + br) * K + bkc;

    float acc[8][4] = {};
    float4 pa0, pa1, pb;

    // ---- prologue: tile 0 ----
    if (aValid) {
        pa0 = *reinterpret_cast<const float4*>(aPtr);
        pa1 = *reinterpret_cast<const float4*>(aPtr + 4);
    } else {
        pa0 = make_float4(0.f, 0.f, 0.f, 0.f);
        pa1 = pa0;
    }
    pb = *reinterpret_cast<const float4*>(bPtr);

    {
        As[0][akc + 0][ar] = pa0.x; As[0][akc + 1][ar] = pa0.y;
        As[0][akc + 2][ar] = pa0.z; As[0][akc + 3][ar] = pa0.w;
        As[0][akc + 4][ar] = pa1.x; As[0][akc + 5][ar] = pa1.y;
        As[0][akc + 6][ar] = pa1.z; As[0][akc + 7][ar] = pa1.w;
        Bs[0][bkc + 0][br] = pb.x;  Bs[0][bkc + 1][br] = pb.y;
        Bs[0][bkc + 2][br] = pb.z;  Bs[0][bkc + 3][br] = pb.w;
    }
    __syncthreads();

    const int ntiles = K >> 4;
    int buf = 0;
    for (int t = 0; t < ntiles; t++) {
        const bool hasNext = (t + 1) < ntiles;
        if (hasNext) {
            const int k0n = (t + 1) << 4;
            if (aValid) {
                pa0 = *reinterpret_cast<const float4*>(aPtr + k0n);
                pa1 = *reinterpret_cast<const float4*>(aPtr + k0n + 4);
            }
            pb = *reinterpret_cast<const float4*>(bPtr + k0n);
        }

        #pragma unroll
        for (int kk = 0; kk < 16; kk++) {
            const float4 a0 = *reinterpret_cast<const float4*>(&As[buf][kk][ty * 4]);
            const float4 a1 = *reinterpret_cast<const float4*>(&As[buf][kk][64 + ty * 4]);
            const float4 b0 = *reinterpret_cast<const float4*>(&Bs[buf][kk][tx * 4]);
            float a[8] = {a0.x, a0.y, a0.z, a0.w, a1.x, a1.y, a1.z, a1.w};
            float b[4] = {b0.x, b0.y, b0.z, b0.w};
            #pragma unroll
            for (int i = 0; i < 8; i++)
                #pragma unroll
                for (int j = 0; j < 4; j++) acc[i][j] += a[i] * b[j];
        }

        if (hasNext) {
            const int nb = buf ^ 1;
            As[nb][akc + 0][ar] = pa0.x; As[nb][akc + 1][ar] = pa0.y;
            As[nb][akc + 2][ar] = pa0.z; As[nb][akc + 3][ar] = pa0.w;
            As[nb][akc + 4][ar] = pa1.x; As[nb][akc + 5][ar] = pa1.y;
            As[nb][akc + 6][ar] = pa1.z; As[nb][akc + 7][ar] = pa1.w;
            Bs[nb][bkc + 0][br] = pb.x;  Bs[nb][bkc + 1][br] = pb.y;
            Bs[nb][bkc + 2][br] = pb.z;  Bs[nb][bkc + 3][br] = pb.w;
            __syncthreads();
            buf = nb;
        }
    }

    // ---- epilogue ----
    const float4 bv = *reinterpret_cast<const float4*>(&bias[bn + tx * 4]);
    const float bias4[4] = {bv.x, bv.y, bv.z, bv.w};
    #pragma unroll
    for (int i = 0; i < 8; i++) {
        const int gm = bm + ((i < 4) ? (ty * 4 + i) : (64 + ty * 4 + (i - 4)));
        if (gm >= M) continue;
        float fl = 1.f;
        if (EPI == 2) fl = flag[gm / flagdiv];
        float4 o;
        float v[4];
        #pragma unroll
        for (int j = 0; j < 4; j++) {
            float x = acc[i][j] + bias4[j];
            if (EPI == 1) x = 0.5f * x * (1.f + erff(x * 0.70710678118654752440f));
            if (EPI == 2) x *= fl;
            v[j] = x;
        }
        o.x = v[0]; o.y = v[1]; o.z = v[2]; o.w = v[3];
        *reinterpret_cast<float4*>(&C[(size_t)gm * N + bn + tx * 4]) = o;
    }
}

// ---------------- inverse norm per relation ----------------
__global__ void invnorm_kernel() {
    const int r = blockIdx.x;
    __shared__ float red[4];
    float s = 0.f;
    for (int d = threadIdx.x; d < D_; d += 128) {
        float x = g_proj[(size_t)r * D_ + d];
        s += x * x;
    }
    s = warpSum(s);
    if ((threadIdx.x & 31) == 0) red[threadIdx.x >> 5] = s;
    __syncthreads();
    if (threadIdx.x == 0) {
        float t = red[0] + red[1] + red[2] + red[3];
        g_invn[r] = 1.f / fmaxf(sqrtf(t), 1e-12f);
    }
}

// ---------------- per-edge: sims, top-k, agg, init states ----------------
__global__ void sims_kernel(const int* __restrict__ eids, const int* __restrict__ nids) {
    const int row = blockIdx.x;               // b*E + e
    __shared__ float rv[D_];
    __shared__ float sims[N_];
    __shared__ int   nid_s[N_];
    __shared__ int   sel[K_];
    const int eid = eids[row];
    for (int d = threadIdx.x; d < D_; d += 256) rv[d] = g_proj[(size_t)eid * D_ + d];
    if (threadIdx.x < N_) nid_s[threadIdx.x] = nids[(size_t)row * N_ + threadIdx.x];
    __syncthreads();

    const int g = threadIdx.x >> 3, sub = threadIdx.x & 7;   // 32 groups x 8 threads
    const int nid = nid_s[g];
    const float* np = &g_proj[(size_t)nid * D_];
    float acc = 0.f;
    for (int d = sub; d < D_; d += 8) acc += np[d] * rv[d];
    acc += __shfl_down_sync(0xFFFFFFFFu, acc, 4, 8);
    acc += __shfl_down_sync(0xFFFFFFFFu, acc, 2, 8);
    acc += __shfl_down_sync(0xFFFFFFFFu, acc, 1, 8);
    if (sub == 0) sims[g] = acc * g_invn[nid] * g_invn[eid];
    __syncthreads();

    if (threadIdx.x == 0) {       // stable top-K (lowest index wins on ties, like lax.top_k)
        unsigned used = 0;
        for (int k = 0; k < K_; k++) {
            float best = -FLT_MAX; int bi = 0;
            for (int n = 0; n < N_; n++)
                if (!((used >> n) & 1u) && sims[n] > best) { best = sims[n]; bi = n; }
            used |= 1u << bi;
            sel[k] = nid_s[bi];
        }
    }
    __syncthreads();

    for (int d = threadIdx.x; d < D_; d += 256) {
        float s = 0.f;
        #pragma unroll
        for (int k = 0; k < K_; k++) s += g_proj[(size_t)sel[k] * D_ + d];
        g_agg[(size_t)row * D_ + d]    = s * (1.f / K_);
        g_states[(size_t)row * D_ + d] = rv[d];
    }
}

// ---------------- residual add + LayerNorm (+ optional mask) ----------------
__global__ void addln_kernel(float* __restrict__ states, const float* __restrict__ delta,
                             const float* __restrict__ gam, const float* __restrict__ bet,
                             const float* __restrict__ mask, int useMask)
{
    const int row = blockIdx.x;
    __shared__ float xs[D_];
    __shared__ float red[8];
    float s = 0.f;
    #pragma unroll
    for (int i = 0; i < 2; i++) {
        int d = threadIdx.x + i * 256;
        float x = states[(size_t)row * D_ + d] + delta[(size_t)row * D_ + d];
        xs[d] = x; s += x;
    }
    s = blockSum256(s, red);
    const float mu = s * (1.f / D_);
    float v = 0.f;
    #pragma unroll
    for (int i = 0; i < 2; i++) {
        int d = threadIdx.x + i * 256;
        float t = xs[d] - mu; v += t * t;
    }
    v = blockSum256(v, red) * (1.f / D_);
    const float r = rsqrtf(v + 1e-5f);
    const float mk = useMask ? mask[row] : 1.f;
    #pragma unroll
    for (int i = 0; i < 2; i++) {
        int d = threadIdx.x + i * 256;
        states[(size_t)row * D_ + d] = ((xs[d] - mu) * r * gam[d] + bet[d]) * mk;
    }
}

// ---------------- per-batch edge-count flag ----------------
__global__ void flag_kernel(const float* __restrict__ mask) {
    const int b = blockIdx.x;
    __shared__ float red[8];
    float s = mask[b * E_ + threadIdx.x];
    s = blockSum256(s, red);
    if (threadIdx.x == 0) g_flag[b] = (s == 0.f) ? 0.f : 1.f;
}

// ---------------- memory-token cross attention ----------------
__global__ void attn_kernel(const float* __restrict__ mask) {
    const int b = blockIdx.x / M_, m = blockIdx.x % M_;
    __shared__ float qh[DH_];
    __shared__ float w[E_];
    __shared__ float red[8];
    const int tid = threadIdx.x;                    // == e (E_ == 256)
    const float scale = 0.125f;                     // 1/sqrt(64)
    const float mk = mask[b * E_ + tid];

    for (int h = 0; h < H_; h++) {
        if (tid < DH_) qh[tid] = g_qbuf[(size_t)m * D_ + h * DH_ + tid];
        __syncthreads();
        const float4* kp4 = reinterpret_cast<const float4*>(
            &g_kbuf[((size_t)(b * E_ + tid)) * D_ + h * DH_]);
        const float4* qh4 = reinterpret_cast<const float4*>(qh);
        float s = 0.f;
        #pragma unroll
        for (int d = 0; d < DH_ / 4; d++) {
            float4 kv = kp4[d], qv = qh4[d];
            s += kv.x * qv.x + kv.y * qv.y + kv.z * qv.z + kv.w * qv.w;
        }
        s *= scale;
        if (mk == 0.f) s = -FLT_MAX;
        float mx = blockMax256(s, red);
        float e  = expf(s - mx);
        float sm = blockSum256(e, red);
        w[tid] = e / sm;
        __syncthreads();
        if (tid < DH_) {
            float acc = 0.f;
            #pragma unroll 4
            for (int e2 = 0; e2 < E_; e2++)
                acc += w[e2] * g_vbuf[((size_t)(b * E_ + e2)) * D_ + h * DH_ + tid];
            g_mem[((size_t)(b * M_ + m)) * D_ + h * DH_ + tid] = acc;
        }
        __syncthreads();
    }
}

// ---------------- host side ----------------
static inline void run_gemm(int epi, const float* A, const float* W, const float* bias,
                            float* C, int M, int N, int K,
                            const float* flag = nullptr, int flagdiv = 1)
{
    dim3 grid(N / 64, (M + 127) / 128);
    dim3 blk(256);
    if (epi == 0)      gemm_kernel<0><<<grid, blk>>>(A, W, bias, C, M, N, K, flag, flagdiv);
    else if (epi == 1) gemm_kernel<1><<<grid, blk>>>(A, W, bias, C, M, N, K, flag, flagdiv);
    else               gemm_kernel<2><<<grid, blk>>>(A, W, bias, C, M, N, K, flag, flagdiv);
}

extern "C" void kernel_launch(void* const* d_in, const int* in_sizes, int n_in,
                              void* d_out, int out_size)
{
    const int*   eids  = (const int*)  d_in[0];
    const int*   nids  = (const int*)  d_in[1];
    const float* mask  = (const float*)d_in[2];
    const float* rel   = (const float*)d_in[3];
    const float* rp_w  = (const float*)d_in[4];
    const float* rp_b  = (const float*)d_in[5];
    const float* vw    = (const float*)d_in[6];
    const float* vb    = (const float*)d_in[7];
    const float* ow    = (const float*)d_in[8];
    const float* ob    = (const float*)d_in[9];
    const float* n1g   = (const float*)d_in[10];
    const float* n1b   = (const float*)d_in[11];
    const float* n2g   = (const float*)d_in[12];
    const float* n2b   = (const float*)d_in[13];
    const float* w1    = (const float*)d_in[14];
    const float* b1    = (const float*)d_in[15];
    const float* w2    = (const float*)d_in[16];
    const float* b2    = (const float*)d_in[17];
    const float* memq  = (const float*)d_in[18];
    const float* qw    = (const float*)d_in[19];
    const float* qb    = (const float*)d_in[20];
    const float* kw    = (const float*)d_in[21];
    const float* kb    = (const float*)d_in[22];
    const float* vw2   = (const float*)d_in[23];
    const float* vb2   = (const float*)d_in[24];
    const float* tow   = (const float*)d_in[25];
    const float* tob   = (const float*)d_in[26];
    const float* pw    = (const float*)d_in[27];
    const float* pb    = (const float*)d_in[28];
    float* out = (float*)d_out;

    float *p_proj, *p_agg, *p_states, *p_t1, *p_t2, *p_hid, *p_k, *p_v, *p_q, *p_mem, *p_memo, *p_flag;
    cudaGetSymbolAddress((void**)&p_proj,   g_proj);
    cudaGetSymbolAddress((void**)&p_agg,    g_agg);
    cudaGetSymbolAddress((void**)&p_states, g_states);
    cudaGetSymbolAddress((void**)&p_t1,     g_t1);
    cudaGetSymbolAddress((void**)&p_t2,     g_t2);
    cudaGetSymbolAddress((void**)&p_hid,    g_hid);
    cudaGetSymbolAddress((void**)&p_k,      g_kbuf);
    cudaGetSymbolAddress((void**)&p_v,      g_vbuf);
    cudaGetSymbolAddress((void**)&p_q,      g_qbuf);
    cudaGetSymbolAddress((void**)&p_mem,    g_mem);
    cudaGetSymbolAddress((void**)&p_memo,   g_memo);
    cudaGetSymbolAddress((void**)&p_flag,   g_flag);

    // 1) relation table: proj_rel = rel_emb @ rp_w^T + rp_b   [2000,512]
    run_gemm(0, rel, rp_w, rp_b, p_proj, R_, D_, RD_);
    // 2) per-relation inverse norms
    invnorm_kernel<<<R_, 128>>>();
    // 3) sims + top-k + agg + states init
    sims_kernel<<<BE_, 256>>>(eids, nids);

    // 4) relation-context layers
    for (int l = 0; l < L_; l++) {
        run_gemm(0, p_agg, vw + (size_t)l * D_ * D_, vb + l * D_, p_t1, BE_, D_, D_);
        run_gemm(0, p_t1,  ow + (size_t)l * D_ * D_, ob + l * D_, p_t2, BE_, D_, D_);
        addln_kernel<<<BE_, 256>>>(p_states, p_t2, n1g + l * D_, n1b + l * D_, mask, 0);
        run_gemm(1, p_states, w1 + (size_t)l * FF_ * D_, b1 + l * FF_, p_hid, BE_, FF_, D_);
        run_gemm(0, p_hid,    w2 + (size_t)l * D_ * FF_, b2 + l * D_,  p_t2,  BE_, D_, FF_);
        addln_kernel<<<BE_, 256>>>(p_states, p_t2, n2g + l * D_, n2b + l * D_, mask, 1);
    }

    // 5) tokenizer projections
    run_gemm(0, memq,     qw,  qb,  p_q, M_,  D_, D_);
    run_gemm(0, p_states, kw,  kb,  p_k, BE_, D_, D_);
    run_gemm(0, p_states, vw2, vb2, p_v, BE_, D_, D_);

    // 6) no-edge flags + cross attention
    flag_kernel<<<B_, 256>>>(mask);
    attn_kernel<<<B_ * M_, 256>>>(mask);

    // 7) memory out-proj (zeroed for no-edge rows) + final LLM projection
    run_gemm(2, p_mem,  tow, tob, p_memo, B_ * M_, D_,  D_, p_flag, M_);
    run_gemm(0, p_memo, pw,  pb,  out,    B_ * M_, HL_, D_);
}

// round 8
// speedup vs baseline: 1.7399x; 1.5568x over previous
#include <cuda_runtime.h>
#include <cuda_bf16.h>
#include <math.h>
#include <float.h>
#include <stdint.h>

// Problem constants
#define B_   8
#define E_   256
#define N_   32
#define D_   512
#define RD_  768
#define R_   2000
#define L_   2
#define K_   8
#define M_   32
#define H_   8
#define DH_  64
#define HL_  4096
#define BE_  (B_*E_)     // 2048
#define FF_  (4*D_)      // 2048

// ---------------- fp32 scratch ----------------
__device__ float g_proj [R_*D_];
__device__ float g_invn [R_];
__device__ float g_agg  [BE_*D_];
__device__ float g_states[BE_*D_];
__device__ float g_t1   [BE_*D_];
__device__ float g_t2   [BE_*D_];
__device__ float g_hid  [BE_*FF_];
__device__ float g_kbuf [BE_*D_];
__device__ float g_vbuf [BE_*D_];
__device__ float g_qbuf [128*D_];      // q GEMM writes 128 padded rows
__device__ float g_mem  [B_*M_*D_];
__device__ float g_memo [B_*M_*D_];
__device__ float g_flag [B_];

// ---------------- bf16 K-tripled buffers: A'=[Ah|Ah|Al], W'=[Wh|Wl|Wh] ----------------
__device__ __align__(16) __nv_bfloat16 c_agg [BE_*3*D_];
__device__ __align__(16) __nv_bfloat16 c_t1  [BE_*3*D_];
__device__ __align__(16) __nv_bfloat16 c_st  [BE_*3*D_];
__device__ __align__(16) __nv_bfloat16 c_hid [BE_*3*FF_];
__device__ __align__(16) __nv_bfloat16 c_mq  [128*3*D_];
__device__ __align__(16) __nv_bfloat16 c_mem [256*3*D_];
__device__ __align__(16) __nv_bfloat16 c_memo[256*3*D_];
__device__ __align__(16) __nv_bfloat16 c_vw  [L_*D_*3*D_];
__device__ __align__(16) __nv_bfloat16 c_ow  [L_*D_*3*D_];
__device__ __align__(16) __nv_bfloat16 c_w1  [L_*FF_*3*D_];
__device__ __align__(16) __nv_bfloat16 c_w2  [L_*D_*3*FF_];
__device__ __align__(16) __nv_bfloat16 c_qw  [D_*3*D_];
__device__ __align__(16) __nv_bfloat16 c_kw  [D_*3*D_];
__device__ __align__(16) __nv_bfloat16 c_v2  [D_*3*D_];
__device__ __align__(16) __nv_bfloat16 c_tw  [D_*3*D_];
__device__ __align__(16) __nv_bfloat16 c_pw  [HL_*3*D_];

// ---------------- helpers ----------------
__device__ __forceinline__ uint32_t smem_u32(const void* p) {
    uint32_t a;
    asm("{ .reg .u64 t; cvta.to.shared.u64 t, %1; cvt.u32.u64 %0, t; }" : "=r"(a) : "l"(p));
    return a;
}
#define SWZ(x) ((x) ^ (((x) >> 3) & 0x70))

__device__ __forceinline__ void ldsm4(uint32_t r[4], uint32_t addr) {
    asm volatile("ldmatrix.sync.aligned.m8n8.x4.shared.b16 {%0,%1,%2,%3}, [%4];"
        : "=r"(r[0]), "=r"(r[1]), "=r"(r[2]), "=r"(r[3]) : "r"(addr));
}
__device__ __forceinline__ void mma16816(float c[4], const uint32_t a[4],
                                         uint32_t b0, uint32_t b1) {
    asm volatile("mma.sync.aligned.m16n8k16.row.col.f32.bf16.bf16.f32 "
        "{%0,%1,%2,%3}, {%4,%5,%6,%7}, {%8,%9}, {%0,%1,%2,%3};"
        : "+f"(c[0]), "+f"(c[1]), "+f"(c[2]), "+f"(c[3])
        : "r"(a[0]), "r"(a[1]), "r"(a[2]), "r"(a[3]), "r"(b0), "r"(b1));
}
#define CP_ASYNC16(smaddr, gptr) \
    asm volatile("cp.async.cg.shared.global [%0], [%1], 16;" :: "r"(smaddr), "l"(gptr))
#define CP_COMMIT() asm volatile("cp.async.commit_group;" ::: "memory")
#define CP_WAIT1()  asm volatile("cp.async.wait_group 1;" ::: "memory")

#define STAGE_BYTES 24576
#define W_OFF 16384
#define TM_SMEM (3*STAGE_BYTES)

// ================= bf16 mma.sync GEMM: C[M,N] = A'[M,K3] @ W'[N,K3]^T + bias =================
// Tile 128x64, 8 warps (32x32 each), K chunks of 64, 3-stage cp.async pipeline.
// Requires: M%128==0 (padded buffers), N%64==0, K3%64==0, nc>=3.
// EPI: 0 none, 1 exact GELU, 2 flag-mul
template<int EPI>
__global__ __launch_bounds__(256)
void tmma_kernel(const __nv_bfloat16* __restrict__ A, const __nv_bfloat16* __restrict__ W,
                 const float* __restrict__ bias, float* __restrict__ C,
                 int N, int K3, const float* __restrict__ flag, int flagdiv)
{
    extern __shared__ char smem[];
    const uint32_t sbase = smem_u32(smem);
    const int tid = threadIdx.x, wid = tid >> 5, lane = tid & 31;
    const int wm = wid >> 1, wn = wid & 1;
    const int bm = blockIdx.y * 128, bn = blockIdx.x * 64;
    const int nc = K3 >> 6;

    float acc[2][4][4] = {};

    auto issue_load = [&](int stage, int c) {
        const uint32_t sa = sbase + stage * STAGE_BYTES;
        const size_t koff = (size_t)c * 64;
        #pragma unroll
        for (int i = 0; i < 4; i++) {                 // A: 128 rows x 128B
            int idx = tid + i * 256;
            int row = idx >> 3, kb = (idx & 7) * 16;
            const char* g = (const char*)(A + (size_t)(bm + row) * K3 + koff) + kb;
            CP_ASYNC16(sa + SWZ((uint32_t)(row * 128 + kb)), g);
        }
        #pragma unroll
        for (int i = 0; i < 2; i++) {                 // W: 64 rows x 128B
            int idx = tid + i * 256;
            int row = idx >> 3, kb = (idx & 7) * 16;
            const char* g = (const char*)(W + (size_t)(bn + row) * K3 + koff) + kb;
            CP_ASYNC16(sa + W_OFF + SWZ((uint32_t)(row * 128 + kb)), g);
        }
    };

    issue_load(0, 0); CP_COMMIT();
    issue_load(1, 1); CP_COMMIT();

    for (int c = 0; c < nc; c++) {
        CP_WAIT1();
        __syncthreads();
        if (c + 2 < nc) issue_load((c + 2) % 3, c + 2);
        CP_COMMIT();

        const uint32_t sa = sbase + (c % 3) * STAGE_BYTES;
        #pragma unroll
        for (int kk = 0; kk < 4; kk++) {
            uint32_t a[2][4], b[2][4];
            const int kb = kk * 32 + ((lane >> 4) << 4);
            #pragma unroll
            for (int mi = 0; mi < 2; mi++) {
                int row = wm * 32 + mi * 16 + (lane & 15);
                ldsm4(a[mi], sa + SWZ((uint32_t)(row * 128 + kb)));
            }
            #pragma unroll
            for (int bi = 0; bi < 2; bi++) {
                int row = wn * 32 + bi * 16 + (lane & 15);
                ldsm4(b[bi], sa + W_OFF + SWZ((uint32_t)(row * 128 + kb)));
            }
            #pragma unroll
            for (int mi = 0; mi < 2; mi++)
                #pragma unroll
                for (int j = 0; j < 4; j++)
                    mma16816(acc[mi][j], a[mi], b[j >> 1][j & 1], b[j >> 1][2 + (j & 1)]);
        }
    }

    // ---- epilogue ----
    const int r = lane >> 2, cp2 = (lane & 3) * 2;
    #pragma unroll
    for (int mi = 0; mi < 2; mi++) {
        #pragma unroll
        for (int half = 0; half < 2; half++) {
            const int gm = bm + wm * 32 + mi * 16 + half * 8 + r;
            float fl = 1.f;
            if (EPI == 2) fl = flag[gm / flagdiv];
            float* crow = C + (size_t)gm * N + bn + wn * 32;
            #pragma unroll
            for (int j = 0; j < 4; j++) {
                const float2 bv = *(const float2*)(bias + bn + wn * 32 + j * 8 + cp2);
                float v0 = acc[mi][j][half * 2 + 0] + bv.x;
                float v1 = acc[mi][j][half * 2 + 1] + bv.y;
                if (EPI == 1) {
                    v0 = 0.5f * v0 * (1.f + erff(v0 * 0.70710678118654752440f));
                    v1 = 0.5f * v1 * (1.f + erff(v1 * 0.70710678118654752440f));
                }
                if (EPI == 2) { v0 *= fl; v1 *= fl; }
                *(float2*)(crow + j * 8 + cp2) = make_float2(v0, v1);
            }
        }
    }
}

// ================= fp32 -> K-tripled bf16 split =================
// modeW=0 (activations): [hi | hi | lo];  modeW=1 (weights): [hi | lo | hi]
__global__ void cvt3_kernel(const float* __restrict__ src, __nv_bfloat16* __restrict__ dst,
                            int K, int rows_src, int rows_tot, int modeW)
{
    const size_t ntot = (size_t)rows_tot * K;
    size_t i = ((size_t)blockIdx.x * blockDim.x + threadIdx.x) * 4;
    const size_t stride = (size_t)gridDim.x * blockDim.x * 4;
    for (; i < ntot; i += stride) {
        const int row = (int)(i / K), k = (int)(i % K);
        float4 x = make_float4(0.f, 0.f, 0.f, 0.f);
        if (row < rows_src) x = *(const float4*)(src + (size_t)row * K + k);
        __nv_bfloat16 h0 = __float2bfloat16(x.x), h1 = __float2bfloat16(x.y);
        __nv_bfloat16 h2 = __float2bfloat16(x.z), h3 = __float2bfloat16(x.w);
        __nv_bfloat162 hp0(h0, h1), hp1(h2, h3);
        __nv_bfloat162 lp0(__float2bfloat16(x.x - __bfloat162float(h0)),
                           __float2bfloat16(x.y - __bfloat162float(h1)));
        __nv_bfloat162 lp1(__float2bfloat16(x.z - __bfloat162float(h2)),
                           __float2bfloat16(x.w - __bfloat162float(h3)));
        __nv_bfloat16* d0 = dst + (size_t)row * 3 * K + k;
        *(__nv_bfloat162*)(d0)     = hp0; *(__nv_bfloat162*)(d0 + 2)         = hp1;
        if (modeW) {
            *(__nv_bfloat162*)(d0 + K)     = lp0; *(__nv_bfloat162*)(d0 + K + 2)     = lp1;
            *(__nv_bfloat162*)(d0 + 2 * K) = hp0; *(__nv_bfloat162*)(d0 + 2 * K + 2) = hp1;
        } else {
            *(__nv_bfloat162*)(d0 + K)     = hp0; *(__nv_bfloat162*)(d0 + K + 2)     = hp1;
            *(__nv_bfloat162*)(d0 + 2 * K) = lp0; *(__nv_bfloat162*)(d0 + 2 * K + 2) = lp1;
        }
    }
}

// ---------------- reductions ----------------
__device__ __forceinline__ float warpSum(float v) {
    #pragma unroll
    for (int o = 16; o; o >>= 1) v += __shfl_down_sync(0xFFFFFFFFu, v, o);
    return v;
}
__device__ __forceinline__ float warpMax(float v) {
    #pragma unroll
    for (int o = 16; o; o >>= 1) v = fmaxf(v, __shfl_down_sync(0xFFFFFFFFu, v, o));
    return v;
}
__device__ __forceinline__ float blockSum256(float v, float* red) {
    float w = warpSum(v);
    if ((threadIdx.x & 31) == 0) red[threadIdx.x >> 5] = w;
    __syncthreads();
    float s = 0.f;
    #pragma unroll
    for (int i = 0; i < 8; i++) s += red[i];
    __syncthreads();
    return s;
}
__device__ __forceinline__ float blockMax256(float v, float* red) {
    float w = warpMax(v);
    if ((threadIdx.x & 31) == 0) red[threadIdx.x >> 5] = w;
    __syncthreads();
    float s = -FLT_MAX;
    #pragma unroll
    for (int i = 0; i < 8; i++) s = fmaxf(s, red[i]);
    __syncthreads();
    return s;
}

// ================= fp32 SGEMM (ONLY the proj table -> top-k selection safety) =================
__global__ __launch_bounds__(256)
void gemm_kernel(const float* __restrict__ A, const float* __restrict__ W,
                 const float* __restrict__ bias, float* __restrict__ C,
                 int M, int N, int K)
{
    __shared__ float As[2][16][132];
    __shared__ float Bs[2][16][68];
    const int bm = blockIdx.y * 128, bn = blockIdx.x * 64;
    const int tid = threadIdx.x;
    const int tx = tid & 15, ty = tid >> 4;
    const int ar  = tid >> 1;
    const int akc = (tid & 1) * 8;
    const int br  = tid >> 2;
    const int bkc = (tid & 3) * 4;
    const bool aValid = (bm + ar) < M;
    const float* __restrict__ aPtr = A + (size_t)(bm + ar) * K + akc;
    const float* __restrict__ bPtr = W + (size_t)(bn + br) * K + bkc;
    float acc[8][4] = {};
    float4 pa0, pa1, pb;
    if (aValid) {
        pa0 = *reinterpret_cast<const float4*>(aPtr);
        pa1 = *reinterpret_cast<const float4*>(aPtr + 4);
    } else { pa0 = make_float4(0.f,0.f,0.f,0.f); pa1 = pa0; }
    pb = *reinterpret_cast<const float4*>(bPtr);
    As[0][akc+0][ar]=pa0.x; As[0][akc+1][ar]=pa0.y; As[0][akc+2][ar]=pa0.z; As[0][akc+3][ar]=pa0.w;
    As[0][akc+4][ar]=pa1.x; As[0][akc+5][ar]=pa1.y; As[0][akc+6][ar]=pa1.z; As[0][akc+7][ar]=pa1.w;
    Bs[0][bkc+0][br]=pb.x;  Bs[0][bkc+1][br]=pb.y;  Bs[0][bkc+2][br]=pb.z;  Bs[0][bkc+3][br]=pb.w;
    __syncthreads();
    const int ntiles = K >> 4;
    int buf = 0;
    for (int t = 0; t < ntiles; t++) {
        const bool hasNext = (t + 1) < ntiles;
        if (hasNext) {
            const int k0n = (t + 1) << 4;
            if (aValid) {
                pa0 = *reinterpret_cast<const float4*>(aPtr + k0n);
                pa1 = *reinterpret_cast<const float4*>(aPtr + k0n + 4);
            }
            pb = *reinterpret_cast<const float4*>(bPtr + k0n);
        }
        #pragma unroll
        for (int kk = 0; kk < 16; kk++) {
            const float4 a0 = *reinterpret_cast<const float4*>(&As[buf][kk][ty * 4]);
            const float4 a1 = *reinterpret_cast<const float4*>(&As[buf][kk][64 + ty * 4]);
            const float4 b0 = *reinterpret_cast<const float4*>(&Bs[buf][kk][tx * 4]);
            float a[8] = {a0.x, a0.y, a0.z, a0.w, a1.x, a1.y, a1.z, a1.w};
            float b[4] = {b0.x, b0.y, b0.z, b0.w};
            #pragma unroll
            for (int i = 0; i < 8; i++)
                #pragma unroll
                for (int j = 0; j < 4; j++) acc[i][j] += a[i] * b[j];
        }
        if (hasNext) {
            const int nb = buf ^ 1;
            As[nb][akc+0][ar]=pa0.x; As[nb][akc+1][ar]=pa0.y; As[nb][akc+2][ar]=pa0.z; As[nb][akc+3][ar]=pa0.w;
            As[nb][akc+4][ar]=pa1.x; As[nb][akc+5][ar]=pa1.y; As[nb][akc+6][ar]=pa1.z; As[nb][akc+7][ar]=pa1.w;
            Bs[nb][bkc+0][br]=pb.x;  Bs[nb][bkc+1][br]=pb.y;  Bs[nb][bkc+2][br]=pb.z;  Bs[nb][bkc+3][br]=pb.w;
            __syncthreads();
            buf = nb;
        }
    }
    const float4 bv = *reinterpret_cast<const float4*>(&bias[bn + tx * 4]);
    const float bias4[4] = {bv.x, bv.y, bv.z, bv.w};
    #pragma unroll
    for (int i = 0; i < 8; i++) {
        const int gm = bm + ((i < 4) ? (ty * 4 + i) : (64 + ty * 4 + (i - 4)));
        if (gm >= M) continue;
        float4 o;
        o.x = acc[i][0] + bias4[0]; o.y = acc[i][1] + bias4[1];
        o.z = acc[i][2] + bias4[2]; o.w = acc[i][3] + bias4[3];
        *reinterpret_cast<float4*>(&C[(size_t)gm * N + bn + tx * 4]) = o;
    }
}

// ---------------- inverse norm per relation ----------------
__global__ void invnorm_kernel() {
    const int r = blockIdx.x;
    __shared__ float red[4];
    float s = 0.f;
    for (int d = threadIdx.x; d < D_; d += 128) {
        float x = g_proj[(size_t)r * D_ + d];
        s += x * x;
    }
    s = warpSum(s);
    if ((threadIdx.x & 31) == 0) red[threadIdx.x >> 5] = s;
    __syncthreads();
    if (threadIdx.x == 0) {
        float t = red[0] + red[1] + red[2] + red[3];
        g_invn[r] = 1.f / fmaxf(sqrtf(t), 1e-12f);
    }
}

// ---------------- per-edge: sims, top-k, agg, init states ----------------
__global__ void sims_kernel(const int* __restrict__ eids, const int* __restrict__ nids) {
    const int row = blockIdx.x;
    __shared__ float rv[D_];
    __shared__ float sims[N_];
    __shared__ int   nid_s[N_];
    __shared__ int   sel[K_];
    const int eid = eids[row];
    for (int d = threadIdx.x; d < D_; d += 256) rv[d] = g_proj[(size_t)eid * D_ + d];
    if (threadIdx.x < N_) nid_s[threadIdx.x] = nids[(size_t)row * N_ + threadIdx.x];
    __syncthreads();

    const int g = threadIdx.x >> 3, sub = threadIdx.x & 7;
    const int nid = nid_s[g];
    const float* np = &g_proj[(size_t)nid * D_];
    float acc = 0.f;
    for (int d = sub; d < D_; d += 8) acc += np[d] * rv[d];
    acc += __shfl_down_sync(0xFFFFFFFFu, acc, 4, 8);
    acc += __shfl_down_sync(0xFFFFFFFFu, acc, 2, 8);
    acc += __shfl_down_sync(0xFFFFFFFFu, acc, 1, 8);
    if (sub == 0) sims[g] = acc * g_invn[nid] * g_invn[eid];
    __syncthreads();

    if (threadIdx.x == 0) {
        unsigned used = 0;
        for (int k = 0; k < K_; k++) {
            float best = -FLT_MAX; int bi = 0;
            for (int n = 0; n < N_; n++)
                if (!((used >> n) & 1u) && sims[n] > best) { best = sims[n]; bi = n; }
            used |= 1u << bi;
            sel[k] = nid_s[bi];
        }
    }
    __syncthreads();

    for (int d = threadIdx.x; d < D_; d += 256) {
        float s = 0.f;
        #pragma unroll
        for (int k = 0; k < K_; k++) s += g_proj[(size_t)sel[k] * D_ + d];
        g_agg[(size_t)row * D_ + d]    = s * (1.f / K_);
        g_states[(size_t)row * D_ + d] = rv[d];
    }
}

// ---------------- residual add + LayerNorm (+ optional mask) ----------------
__global__ void addln_kernel(float* __restrict__ states, const float* __restrict__ delta,
                             const float* __restrict__ gam, const float* __restrict__ bet,
                             const float* __restrict__ mask, int useMask)
{
    const int row = blockIdx.x;
    __shared__ float xs[D_];
    __shared__ float red[8];
    float s = 0.f;
    #pragma unroll
    for (int i = 0; i < 2; i++) {
        int d = threadIdx.x + i * 256;
        float x = states[(size_t)row * D_ + d] + delta[(size_t)row * D_ + d];
        xs[d] = x; s += x;
    }
    s = blockSum256(s, red);
    const float mu = s * (1.f / D_);
    float v = 0.f;
    #pragma unroll
    for (int i = 0; i < 2; i++) {
        int d = threadIdx.x + i * 256;
        float t = xs[d] - mu; v += t * t;
    }
    v = blockSum256(v, red) * (1.f / D_);
    const float r = rsqrtf(v + 1e-5f);
    const float mk = useMask ? mask[row] : 1.f;
    #pragma unroll
    for (int i = 0; i < 2; i++) {
        int d = threadIdx.x + i * 256;
        states[(size_t)row * D_ + d] = ((xs[d] - mu) * r * gam[d] + bet[d]) * mk;
    }
}

// ---------------- per-batch edge-count flag ----------------
__global__ void flag_kernel(const float* __restrict__ mask) {
    const int b = blockIdx.x;
    __shared__ float red[8];
    float s = mask[b * E_ + threadIdx.x];
    s = blockSum256(s, red);
    if (threadIdx.x == 0) g_flag[b] = (s == 0.f) ? 0.f : 1.f;
}

// ---------------- memory-token cross attention ----------------
__global__ void attn_kernel(const float* __restrict__ mask) {
    const int b = blockIdx.x / M_, m = blockIdx.x % M_;
    __shared__ float qh[DH_];
    __shared__ float w[E_];
    __shared__ float red[8];
    const int tid = threadIdx.x;
    const float scale = 0.125f;
    const float mk = mask[b * E_ + tid];

    for (int h = 0; h < H_; h++) {
        if (tid < DH_) qh[tid] = g_qbuf[(size_t)m * D_ + h * DH_ + tid];
        __syncthreads();
        const float4* kp4 = reinterpret_cast<const float4*>(
            &g_kbuf[((size_t)(b * E_ + tid)) * D_ + h * DH_]);
        const float4* qh4 = reinterpret_cast<const float4*>(qh);
        float s = 0.f;
        #pragma unroll
        for (int d = 0; d < DH_ / 4; d++) {
            float4 kv = kp4[d], qv = qh4[d];
            s += kv.x * qv.x + kv.y * qv.y + kv.z * qv.z + kv.w * qv.w;
        }
        s *= scale;
        if (mk == 0.f) s = -FLT_MAX;
        float mx = blockMax256(s, red);
        float e  = expf(s - mx);
        float sm = blockSum256(e, red);
        w[tid] = e / sm;
        __syncthreads();
        if (tid < DH_) {
            float acc = 0.f;
            #pragma unroll 4
            for (int e2 = 0; e2 < E_; e2++)
                acc += w[e2] * g_vbuf[((size_t)(b * E_ + e2)) * D_ + h * DH_ + tid];
            g_mem[((size_t)(b * M_ + m)) * D_ + h * DH_ + tid] = acc;
        }
        __syncthreads();
    }
}

// ---------------- host side ----------------
static inline void run_cvt3(const float* src, __nv_bfloat16* dst, int K,
                            int rows_src, int rows_tot, int modeW)
{
    size_t n4 = (size_t)rows_tot * K / 4;
    int blocks = (int)((n4 + 255) / 256);
    if (blocks > 2048) blocks = 2048;
    cvt3_kernel<<<blocks, 256>>>(src, dst, K, rows_src, rows_tot, modeW);
}

template<int EPI>
static inline void run_tmma(const __nv_bfloat16* A, const __nv_bfloat16* W, const float* bias,
                            float* C, int Mrows, int N, int K3,
                            const float* flag = nullptr, int flagdiv = 1)
{
    cudaFuncSetAttribute(tmma_kernel<EPI>, cudaFuncAttributeMaxDynamicSharedMemorySize, TM_SMEM);
    dim3 grid(N / 64, Mrows / 128);
    tmma_kernel<EPI><<<grid, 256, TM_SMEM>>>(A, W, bias, C, N, K3, flag, flagdiv);
}

extern "C" void kernel_launch(void* const* d_in, const int* in_sizes, int n_in,
                              void* d_out, int out_size)
{
    const int*   eids  = (const int*)  d_in[0];
    const int*   nids  = (const int*)  d_in[1];
    const float* mask  = (const float*)d_in[2];
    const float* rel   = (const float*)d_in[3];
    const float* rp_w  = (const float*)d_in[4];
    const float* rp_b  = (const float*)d_in[5];
    const float* vw    = (const float*)d_in[6];
    const float* vb    = (const float*)d_in[7];
    const float* ow    = (const float*)d_in[8];
    const float* ob    = (const float*)d_in[9];
    const float* n1g   = (const float*)d_in[10];
    const float* n1b   = (const float*)d_in[11];
    const float* n2g   = (const float*)d_in[12];
    const float* n2b   = (const float*)d_in[13];
    const float* w1    = (const float*)d_in[14];
    const float* b1    = (const float*)d_in[15];
    const float* w2    = (const float*)d_in[16];
    const float* b2    = (const float*)d_in[17];
    const float* memq  = (const float*)d_in[18];
    const float* qw    = (const float*)d_in[19];
    const float* qb    = (const float*)d_in[20];
    const float* kw    = (const float*)d_in[21];
    const float* kb    = (const float*)d_in[22];
    const float* vw2   = (const float*)d_in[23];
    const float* vb2   = (const float*)d_in[24];
    const float* tow   = (const float*)d_in[25];
    const float* tob   = (const float*)d_in[26];
    const float* pw    = (const float*)d_in[27];
    const float* pb    = (const float*)d_in[28];
    float* out = (float*)d_out;

    float *p_proj, *p_agg, *p_states, *p_t1, *p_t2, *p_hid, *p_k, *p_v, *p_q, *p_mem, *p_memo, *p_flag;
    cudaGetSymbolAddress((void**)&p_proj,   g_proj);
    cudaGetSymbolAddress((void**)&p_agg,    g_agg);
    cudaGetSymbolAddress((void**)&p_states, g_states);
    cudaGetSymbolAddress((void**)&p_t1,     g_t1);
    cudaGetSymbolAddress((void**)&p_t2,     g_t2);
    cudaGetSymbolAddress((void**)&p_hid,    g_hid);
    cudaGetSymbolAddress((void**)&p_k,      g_kbuf);
    cudaGetSymbolAddress((void**)&p_v,      g_vbuf);
    cudaGetSymbolAddress((void**)&p_q,      g_qbuf);
    cudaGetSymbolAddress((void**)&p_mem,    g_mem);
    cudaGetSymbolAddress((void**)&p_memo,   g_memo);
    cudaGetSymbolAddress((void**)&p_flag,   g_flag);

    __nv_bfloat16 *x_agg,*x_t1,*x_st,*x_hid,*x_mq,*x_mem,*x_memo;
    __nv_bfloat16 *x_vw,*x_ow,*x_w1,*x_w2,*x_qw,*x_kw,*x_v2,*x_tw,*x_pw;
    cudaGetSymbolAddress((void**)&x_agg,  c_agg);
    cudaGetSymbolAddress((void**)&x_t1,   c_t1);
    cudaGetSymbolAddress((void**)&x_st,   c_st);
    cudaGetSymbolAddress((void**)&x_hid,  c_hid);
    cudaGetSymbolAddress((void**)&x_mq,   c_mq);
    cudaGetSymbolAddress((void**)&x_mem,  c_mem);
    cudaGetSymbolAddress((void**)&x_memo, c_memo);
    cudaGetSymbolAddress((void**)&x_vw,   c_vw);
    cudaGetSymbolAddress((void**)&x_ow,   c_ow);
    cudaGetSymbolAddress((void**)&x_w1,   c_w1);
    cudaGetSymbolAddress((void**)&x_w2,   c_w2);
    cudaGetSymbolAddress((void**)&x_qw,   c_qw);
    cudaGetSymbolAddress((void**)&x_kw,   c_kw);
    cudaGetSymbolAddress((void**)&x_v2,   c_v2);
    cudaGetSymbolAddress((void**)&x_tw,   c_tw);
    cudaGetSymbolAddress((void**)&x_pw,   c_pw);

    // Weight conversions (hi|lo|hi along K)
    run_cvt3(vw,  x_vw, D_,  L_*D_,  L_*D_,  1);
    run_cvt3(ow,  x_ow, D_,  L_*D_,  L_*D_,  1);
    run_cvt3(w1,  x_w1, D_,  L_*FF_, L_*FF_, 1);
    run_cvt3(w2,  x_w2, FF_, L_*D_,  L_*D_,  1);
    run_cvt3(qw,  x_qw, D_,  D_, D_, 1);
    run_cvt3(kw,  x_kw, D_,  D_, D_, 1);
    run_cvt3(vw2, x_v2, D_,  D_, D_, 1);
    run_cvt3(tow, x_tw, D_,  D_, D_, 1);
    run_cvt3(pw,  x_pw, D_,  HL_, HL_, 1);

    // 1) relation table in exact fp32 (top-k selection safety)
    {
        dim3 grid(D_ / 64, (R_ + 127) / 128);
        gemm_kernel<<<grid, 256>>>(rel, rp_w, rp_b, p_proj, R_, D_, RD_);
    }
    invnorm_kernel<<<R_, 128>>>();
    sims_kernel<<<BE_, 256>>>(eids, nids);

    run_cvt3(p_agg, x_agg, D_, BE_, BE_, 0);

    // 4) relation-context layers (tensor-core bf16-split GEMMs, K3 = 3K)
    for (int l = 0; l < L_; l++) {
        run_tmma<0>(x_agg, x_vw + (size_t)l*D_*3*D_, vb + l*D_, p_t1, BE_, D_, 3*D_);
        run_cvt3(p_t1, x_t1, D_, BE_, BE_, 0);
        run_tmma<0>(x_t1, x_ow + (size_t)l*D_*3*D_, ob + l*D_, p_t2, BE_, D_, 3*D_);
        addln_kernel<<<BE_, 256>>>(p_states, p_t2, n1g + l*D_, n1b + l*D_, mask, 0);
        run_cvt3(p_states, x_st, D_, BE_, BE_, 0);
        run_tmma<1>(x_st, x_w1 + (size_t)l*FF_*3*D_, b1 + l*FF_, p_hid, BE_, FF_, 3*D_);
        run_cvt3(p_hid, x_hid, FF_, BE_, BE_, 0);
        run_tmma<0>(x_hid, x_w2 + (size_t)l*D_*3*FF_, b2 + l*D_, p_t2, BE_, D_, 3*FF_);
        addln_kernel<<<BE_, 256>>>(p_states, p_t2, n2g + l*D_, n2b + l*D_, mask, 1);
    }

    // 5) tokenizer projections
    run_cvt3(p_states, x_st, D_, BE_, BE_, 0);
    run_tmma<0>(x_st, x_kw, kb,  p_k, BE_, D_, 3*D_);
    run_tmma<0>(x_st, x_v2, vb2, p_v, BE_, D_, 3*D_);
    run_cvt3(memq, x_mq, D_, M_, 128, 0);
    run_tmma<0>(x_mq, x_qw, qb, p_q, 128, D_, 3*D_);

    // 6) no-edge flags + cross attention
    flag_kernel<<<B_, 256>>>(mask);
    attn_kernel<<<B_ * M_, 256>>>(mask);

    // 7) memory out-proj (flag epilogue) + final LLM projection
    run_cvt3(p_mem, x_mem, D_, B_*M_, B_*M_, 0);
    run_tmma<2>(x_mem, x_tw, tob, p_memo, B_*M_, D_, 3*D_, p_flag, M_);
    run_cvt3(p_memo, x_memo, D_, B_*M_, B_*M_, 0);
    run_tmma<0>(x_memo, x_pw, pb, out, B_*M_, HL_, 3*D_);
}

// round 9
// speedup vs baseline: 2.3140x; 1.3300x over previous
#include <cuda_runtime.h>
#include <cuda_bf16.h>
#include <math.h>
#include <float.h>
#include <stdint.h>

// Problem constants
#define B_   8
#define E_   256
#define N_   32
#define D_   512
#define RD_  768
#define R_   2000
#define L_   2
#define K_   8
#define M_   32
#define H_   8
#define DH_  64
#define HL_  4096
#define BE_  (B_*E_)     // 2048
#define FF_  (4*D_)      // 2048

// ---------------- fp32 scratch ----------------
__device__ float g_proj [R_*D_];
__device__ float g_invn [R_];
__device__ float g_states[BE_*D_];
__device__ float g_t2   [BE_*D_];
__device__ float g_kbuf [BE_*D_];
__device__ float g_vbuf [BE_*D_];
__device__ float g_qbuf [128*D_];
__device__ float g_flag [B_];

// ---------------- bf16 K-tripled buffers: A'=[Ah|Ah|Al], W'=[Wh|Wl|Wh] ----------------
__device__ __align__(16) __nv_bfloat16 c_agg [BE_*3*D_];
__device__ __align__(16) __nv_bfloat16 c_t1  [BE_*3*D_];
__device__ __align__(16) __nv_bfloat16 c_st  [BE_*3*D_];
__device__ __align__(16) __nv_bfloat16 c_hid [BE_*3*FF_];
__device__ __align__(16) __nv_bfloat16 c_mq  [128*3*D_];
__device__ __align__(16) __nv_bfloat16 c_mem [256*3*D_];
__device__ __align__(16) __nv_bfloat16 c_memo[256*3*D_];
__device__ __align__(16) __nv_bfloat16 c_vw  [L_*D_*3*D_];
__device__ __align__(16) __nv_bfloat16 c_ow  [L_*D_*3*D_];
__device__ __align__(16) __nv_bfloat16 c_w1  [L_*FF_*3*D_];
__device__ __align__(16) __nv_bfloat16 c_w2  [L_*D_*3*FF_];
__device__ __align__(16) __nv_bfloat16 c_qw  [D_*3*D_];
__device__ __align__(16) __nv_bfloat16 c_kw  [D_*3*D_];
__device__ __align__(16) __nv_bfloat16 c_v2  [D_*3*D_];
__device__ __align__(16) __nv_bfloat16 c_tw  [D_*3*D_];
__device__ __align__(16) __nv_bfloat16 c_pw  [HL_*3*D_];

// ---------------- helpers ----------------
__device__ __forceinline__ uint32_t smem_u32(const void* p) {
    uint32_t a;
    asm("{ .reg .u64 t; cvta.to.shared.u64 t, %1; cvt.u32.u64 %0, t; }" : "=r"(a) : "l"(p));
    return a;
}
#define SWZ(x) ((x) ^ (((x) >> 3) & 0x70))

__device__ __forceinline__ void ldsm4(uint32_t r[4], uint32_t addr) {
    asm volatile("ldmatrix.sync.aligned.m8n8.x4.shared.b16 {%0,%1,%2,%3}, [%4];"
        : "=r"(r[0]), "=r"(r[1]), "=r"(r[2]), "=r"(r[3]) : "r"(addr));
}
__device__ __forceinline__ void mma16816(float c[4], const uint32_t a[4],
                                         uint32_t b0, uint32_t b1) {
    asm volatile("mma.sync.aligned.m16n8k16.row.col.f32.bf16.bf16.f32 "
        "{%0,%1,%2,%3}, {%4,%5,%6,%7}, {%8,%9}, {%0,%1,%2,%3};"
        : "+f"(c[0]), "+f"(c[1]), "+f"(c[2]), "+f"(c[3])
        : "r"(a[0]), "r"(a[1]), "r"(a[2]), "r"(a[3]), "r"(b0), "r"(b1));
}
#define CP_ASYNC16(smaddr, gptr) \
    asm volatile("cp.async.cg.shared.global [%0], [%1], 16;" :: "r"(smaddr), "l"(gptr))
#define CP_COMMIT() asm volatile("cp.async.commit_group;" ::: "memory")
#define CP_WAIT1()  asm volatile("cp.async.wait_group 1;" ::: "memory")

#define STAGE_BYTES 24576
#define W_OFF 16384
#define TM_SMEM (3*STAGE_BYTES)

__device__ __forceinline__ void split_pair(float v0, float v1,
                                           __nv_bfloat162& hp, __nv_bfloat162& lp) {
    __nv_bfloat16 h0 = __float2bfloat16(v0), h1 = __float2bfloat16(v1);
    hp = __nv_bfloat162(h0, h1);
    lp = __nv_bfloat162(__float2bfloat16(v0 - __bfloat162float(h0)),
                        __float2bfloat16(v1 - __bfloat162float(h1)));
}

// ================= bf16 mma.sync GEMM: C = A'[M,K3] @ W'[N,K3]^T + bias =================
// Tile 128x64, 8 warps, K chunks of 64, 3-stage cp.async pipeline.
// EPI: 0 none, 1 exact GELU, 2 flag-mul.  OUT: 0 fp32 C, 1 bf16 triple C3 [hi|hi|lo]
template<int EPI, int OUT>
__global__ __launch_bounds__(256)
void tmma_kernel(const __nv_bfloat16* __restrict__ A, const __nv_bfloat16* __restrict__ W,
                 const float* __restrict__ bias, float* __restrict__ C,
                 __nv_bfloat16* __restrict__ C3,
                 int N, int K3, const float* __restrict__ flag, int flagdiv)
{
    extern __shared__ char smem[];
    const uint32_t sbase = smem_u32(smem);
    const int tid = threadIdx.x, wid = tid >> 5, lane = tid & 31;
    const int wm = wid >> 1, wn = wid & 1;
    const int bm = blockIdx.y * 128, bn = blockIdx.x * 64;
    const int nc = K3 >> 6;

    float acc[2][4][4] = {};

    auto issue_load = [&](int stage, int c) {
        const uint32_t sa = sbase + stage * STAGE_BYTES;
        const size_t koff = (size_t)c * 64;
        #pragma unroll
        for (int i = 0; i < 4; i++) {
            int idx = tid + i * 256;
            int row = idx >> 3, kb = (idx & 7) * 16;
            const char* g = (const char*)(A + (size_t)(bm + row) * K3 + koff) + kb;
            CP_ASYNC16(sa + SWZ((uint32_t)(row * 128 + kb)), g);
        }
        #pragma unroll
        for (int i = 0; i < 2; i++) {
            int idx = tid + i * 256;
            int row = idx >> 3, kb = (idx & 7) * 16;
            const char* g = (const char*)(W + (size_t)(bn + row) * K3 + koff) + kb;
            CP_ASYNC16(sa + W_OFF + SWZ((uint32_t)(row * 128 + kb)), g);
        }
    };

    issue_load(0, 0); CP_COMMIT();
    issue_load(1, 1); CP_COMMIT();

    for (int c = 0; c < nc; c++) {
        CP_WAIT1();
        __syncthreads();
        if (c + 2 < nc) issue_load((c + 2) % 3, c + 2);
        CP_COMMIT();

        const uint32_t sa = sbase + (c % 3) * STAGE_BYTES;
        #pragma unroll
        for (int kk = 0; kk < 4; kk++) {
            uint32_t a[2][4], b[2][4];
            const int kb = kk * 32 + ((lane >> 4) << 4);
            #pragma unroll
            for (int mi = 0; mi < 2; mi++) {
                int row = wm * 32 + mi * 16 + (lane & 15);
                ldsm4(a[mi], sa + SWZ((uint32_t)(row * 128 + kb)));
            }
            #pragma unroll
            for (int bi = 0; bi < 2; bi++) {
                int row = wn * 32 + bi * 16 + (lane & 15);
                ldsm4(b[bi], sa + W_OFF + SWZ((uint32_t)(row * 128 + kb)));
            }
            #pragma unroll
            for (int mi = 0; mi < 2; mi++)
                #pragma unroll
                for (int j = 0; j < 4; j++)
                    mma16816(acc[mi][j], a[mi], b[j >> 1][j & 1], b[j >> 1][2 + (j & 1)]);
        }
    }

    // ---- epilogue ----
    const int r = lane >> 2, cp2 = (lane & 3) * 2;
    #pragma unroll
    for (int mi = 0; mi < 2; mi++) {
        #pragma unroll
        for (int half = 0; half < 2; half++) {
            const int gm = bm + wm * 32 + mi * 16 + half * 8 + r;
            float fl = 1.f;
            if (EPI == 2) fl = flag[gm / flagdiv];
            #pragma unroll
            for (int j = 0; j < 4; j++) {
                const int off = j * 8 + cp2;
                const float2 bv = *(const float2*)(bias + bn + wn * 32 + off);
                float v0 = acc[mi][j][half * 2 + 0] + bv.x;
                float v1 = acc[mi][j][half * 2 + 1] + bv.y;
                if (EPI == 1) {
                    v0 = 0.5f * v0 * (1.f + erff(v0 * 0.70710678118654752440f));
                    v1 = 0.5f * v1 * (1.f + erff(v1 * 0.70710678118654752440f));
                }
                if (EPI == 2) { v0 *= fl; v1 *= fl; }
                if (OUT == 0) {
                    *(float2*)(C + (size_t)gm * N + bn + wn * 32 + off) = make_float2(v0, v1);
                } else {
                    __nv_bfloat162 hp, lp;
                    split_pair(v0, v1, hp, lp);
                    __nv_bfloat16* drow = C3 + (size_t)gm * 3 * N + bn + wn * 32 + off;
                    *(__nv_bfloat162*)(drow)         = hp;
                    *(__nv_bfloat162*)(drow + N)     = hp;
                    *(__nv_bfloat162*)(drow + 2 * N) = lp;
                }
            }
        }
    }
}

// ================= fp32 -> K-tripled bf16 split (weights + mem_q only) =================
// modeW=0 (activations): [hi|hi|lo];  modeW=1 (weights): [hi|lo|hi]
__global__ void cvt3_kernel(const float* __restrict__ src, __nv_bfloat16* __restrict__ dst,
                            int K, int rows_src, int rows_tot, int modeW)
{
    const size_t ntot = (size_t)rows_tot * K;
    size_t i = ((size_t)blockIdx.x * blockDim.x + threadIdx.x) * 4;
    const size_t stride = (size_t)gridDim.x * blockDim.x * 4;
    for (; i < ntot; i += stride) {
        const int row = (int)(i / K), k = (int)(i % K);
        float4 x = make_float4(0.f, 0.f, 0.f, 0.f);
        if (row < rows_src) x = *(const float4*)(src + (size_t)row * K + k);
        __nv_bfloat162 hp0, lp0, hp1, lp1;
        split_pair(x.x, x.y, hp0, lp0);
        split_pair(x.z, x.w, hp1, lp1);
        __nv_bfloat16* d0 = dst + (size_t)row * 3 * K + k;
        *(__nv_bfloat162*)(d0)     = hp0; *(__nv_bfloat162*)(d0 + 2)         = hp1;
        if (modeW) {
            *(__nv_bfloat162*)(d0 + K)     = lp0; *(__nv_bfloat162*)(d0 + K + 2)     = lp1;
            *(__nv_bfloat162*)(d0 + 2 * K) = hp0; *(__nv_bfloat162*)(d0 + 2 * K + 2) = hp1;
        } else {
            *(__nv_bfloat162*)(d0 + K)     = hp0; *(__nv_bfloat162*)(d0 + K + 2)     = hp1;
            *(__nv_bfloat162*)(d0 + 2 * K) = lp0; *(__nv_bfloat162*)(d0 + 2 * K + 2) = lp1;
        }
    }
}

// ---------------- reductions ----------------
__device__ __forceinline__ float warpSum(float v) {
    #pragma unroll
    for (int o = 16; o; o >>= 1) v += __shfl_down_sync(0xFFFFFFFFu, v, o);
    return v;
}
__device__ __forceinline__ float warpMax(float v) {
    #pragma unroll
    for (int o = 16; o; o >>= 1) v = fmaxf(v, __shfl_down_sync(0xFFFFFFFFu, v, o));
    return v;
}
__device__ __forceinline__ float blockSum256(float v, float* red) {
    float w = warpSum(v);
    if ((threadIdx.x & 31) == 0) red[threadIdx.x >> 5] = w;
    __syncthreads();
    float s = 0.f;
    #pragma unroll
    for (int i = 0; i < 8; i++) s += red[i];
    __syncthreads();
    return s;
}
__device__ __forceinline__ float blockMax256(float v, float* red) {
    float w = warpMax(v);
    if ((threadIdx.x & 31) == 0) red[threadIdx.x >> 5] = w;
    __syncthreads();
    float s = -FLT_MAX;
    #pragma unroll
    for (int i = 0; i < 8; i++) s = fmaxf(s, red[i]);
    __syncthreads();
    return s;
}

// ================= fp32 SGEMM (ONLY the proj table -> top-k selection safety) =================
__global__ __launch_bounds__(256)
void gemm_kernel(const float* __restrict__ A, const float* __restrict__ W,
                 const float* __restrict__ bias, float* __restrict__ C,
                 int M, int N, int K)
{
    __shared__ float As[2][16][132];
    __shared__ float Bs[2][16][68];
    const int bm = blockIdx.y * 128, bn = blockIdx.x * 64;
    const int tid = threadIdx.x;
    const int tx = tid & 15, ty = tid >> 4;
    const int ar  = tid >> 1;
    const int akc = (tid & 1) * 8;
    const int br  = tid >> 2;
    const int bkc = (tid & 3) * 4;
    const bool aValid = (bm + ar) < M;
    const float* __restrict__ aPtr = A + (size_t)(bm + ar) * K + akc;
    const float* __restrict__ bPtr = W + (size_t)(bn + br) * K + bkc;
    float acc[8][4] = {};
    float4 pa0, pa1, pb;
    if (aValid) {
        pa0 = *reinterpret_cast<const float4*>(aPtr);
        pa1 = *reinterpret_cast<const float4*>(aPtr + 4);
    } else { pa0 = make_float4(0.f,0.f,0.f,0.f); pa1 = pa0; }
    pb = *reinterpret_cast<const float4*>(bPtr);
    As[0][akc+0][ar]=pa0.x; As[0][akc+1][ar]=pa0.y; As[0][akc+2][ar]=pa0.z; As[0][akc+3][ar]=pa0.w;
    As[0][akc+4][ar]=pa1.x; As[0][akc+5][ar]=pa1.y; As[0][akc+6][ar]=pa1.z; As[0][akc+7][ar]=pa1.w;
    Bs[0][bkc+0][br]=pb.x;  Bs[0][bkc+1][br]=pb.y;  Bs[0][bkc+2][br]=pb.z;  Bs[0][bkc+3][br]=pb.w;
    __syncthreads();
    const int ntiles = K >> 4;
    int buf = 0;
    for (int t = 0; t < ntiles; t++) {
        const bool hasNext = (t + 1) < ntiles;
        if (hasNext) {
            const int k0n = (t + 1) << 4;
            if (aValid) {
                pa0 = *reinterpret_cast<const float4*>(aPtr + k0n);
                pa1 = *reinterpret_cast<const float4*>(aPtr + k0n + 4);
            }
            pb = *reinterpret_cast<const float4*>(bPtr + k0n);
        }
        #pragma unroll
        for (int kk = 0; kk < 16; kk++) {
            const float4 a0 = *reinterpret_cast<const float4*>(&As[buf][kk][ty * 4]);
            const float4 a1 = *reinterpret_cast<const float4*>(&As[buf][kk][64 + ty * 4]);
            const float4 b0 = *reinterpret_cast<const float4*>(&Bs[buf][kk][tx * 4]);
            float a[8] = {a0.x, a0.y, a0.z, a0.w, a1.x, a1.y, a1.z, a1.w};
            float b[4] = {b0.x, b0.y, b0.z, b0.w};
            #pragma unroll
            for (int i = 0; i < 8; i++)
                #pragma unroll
                for (int j = 0; j < 4; j++) acc[i][j] += a[i] * b[j];
        }
        if (hasNext) {
            const int nb = buf ^ 1;
            As[nb][akc+0][ar]=pa0.x; As[nb][akc+1][ar]=pa0.y; As[nb][akc+2][ar]=pa0.z; As[nb][akc+3][ar]=pa0.w;
            As[nb][akc+4][ar]=pa1.x; As[nb][akc+5][ar]=pa1.y; As[nb][akc+6][ar]=pa1.z; As[nb][akc+7][ar]=pa1.w;
            Bs[nb][bkc+0][br]=pb.x;  Bs[nb][bkc+1][br]=pb.y;  Bs[nb][bkc+2][br]=pb.z;  Bs[nb][bkc+3][br]=pb.w;
            __syncthreads();
            buf = nb;
        }
    }
    const float4 bv = *reinterpret_cast<const float4*>(&bias[bn + tx * 4]);
    const float bias4[4] = {bv.x, bv.y, bv.z, bv.w};
    #pragma unroll
    for (int i = 0; i < 8; i++) {
        const int gm = bm + ((i < 4) ? (ty * 4 + i) : (64 + ty * 4 + (i - 4)));
        if (gm >= M) continue;
        float4 o;
        o.x = acc[i][0] + bias4[0]; o.y = acc[i][1] + bias4[1];
        o.z = acc[i][2] + bias4[2]; o.w = acc[i][3] + bias4[3];
        *reinterpret_cast<float4*>(&C[(size_t)gm * N + bn + tx * 4]) = o;
    }
}

// ---------------- inverse norm per relation ----------------
__global__ void invnorm_kernel() {
    const int r = blockIdx.x;
    __shared__ float red[4];
    float s = 0.f;
    for (int d = threadIdx.x; d < D_; d += 128) {
        float x = g_proj[(size_t)r * D_ + d];
        s += x * x;
    }
    s = warpSum(s);
    if ((threadIdx.x & 31) == 0) red[threadIdx.x >> 5] = s;
    __syncthreads();
    if (threadIdx.x == 0) {
        float t = red[0] + red[1] + red[2] + red[3];
        g_invn[r] = 1.f / fmaxf(sqrtf(t), 1e-12f);
    }
}

// ---------------- per-edge: sims, top-k, agg(triple) + states init ----------------
__global__ void sims_kernel(const int* __restrict__ eids, const int* __restrict__ nids) {
    const int row = blockIdx.x;
    __shared__ float rv[D_];
    __shared__ float sims[N_];
    __shared__ int   nid_s[N_];
    __shared__ int   sel[K_];
    const int eid = eids[row];
    for (int d = threadIdx.x; d < D_; d += 256) rv[d] = g_proj[(size_t)eid * D_ + d];
    if (threadIdx.x < N_) nid_s[threadIdx.x] = nids[(size_t)row * N_ + threadIdx.x];
    __syncthreads();

    const int g = threadIdx.x >> 3, sub = threadIdx.x & 7;
    const int nid = nid_s[g];
    const float* np = &g_proj[(size_t)nid * D_];
    float acc = 0.f;
    for (int d = sub; d < D_; d += 8) acc += np[d] * rv[d];
    acc += __shfl_down_sync(0xFFFFFFFFu, acc, 4, 8);
    acc += __shfl_down_sync(0xFFFFFFFFu, acc, 2, 8);
    acc += __shfl_down_sync(0xFFFFFFFFu, acc, 1, 8);
    if (sub == 0) sims[g] = acc * g_invn[nid] * g_invn[eid];
    __syncthreads();

    if (threadIdx.x == 0) {
        unsigned used = 0;
        for (int k = 0; k < K_; k++) {
            float best = -FLT_MAX; int bi = 0;
            for (int n = 0; n < N_; n++)
                if (!((used >> n) & 1u) && sims[n] > best) { best = sims[n]; bi = n; }
            used |= 1u << bi;
            sel[k] = nid_s[bi];
        }
    }
    __syncthreads();

    __nv_bfloat16* arow = c_agg + (size_t)row * 3 * D_;
    for (int d = threadIdx.x; d < D_; d += 256) {
        float s = 0.f;
        #pragma unroll
        for (int k = 0; k < K_; k++) s += g_proj[(size_t)sel[k] * D_ + d];
        const float a = s * (1.f / K_);
        __nv_bfloat16 h = __float2bfloat16(a);
        arow[d]          = h;
        arow[D_ + d]     = h;
        arow[2 * D_ + d] = __float2bfloat16(a - __bfloat162float(h));
        g_states[(size_t)row * D_ + d] = rv[d];
    }
}

// ---------------- residual add + LayerNorm (+ mask) + optional triple out ----------------
__global__ void addln_kernel(float* __restrict__ states, const float* __restrict__ delta,
                             const float* __restrict__ gam, const float* __restrict__ bet,
                             const float* __restrict__ mask, int useMask,
                             __nv_bfloat16* __restrict__ dst3)
{
    const int row = blockIdx.x;
    __shared__ float xs[D_];
    __shared__ float red[8];
    float s = 0.f;
    #pragma unroll
    for (int i = 0; i < 2; i++) {
        int d = threadIdx.x + i * 256;
        float x = states[(size_t)row * D_ + d] + delta[(size_t)row * D_ + d];
        xs[d] = x; s += x;
    }
    s = blockSum256(s, red);
    const float mu = s * (1.f / D_);
    float v = 0.f;
    #pragma unroll
    for (int i = 0; i < 2; i++) {
        int d = threadIdx.x + i * 256;
        float t = xs[d] - mu; v += t * t;
    }
    v = blockSum256(v, red) * (1.f / D_);
    const float r = rsqrtf(v + 1e-5f);
    const float mk = useMask ? mask[row] : 1.f;
    #pragma unroll
    for (int i = 0; i < 2; i++) {
        int d = threadIdx.x + i * 256;
        const float y = ((xs[d] - mu) * r * gam[d] + bet[d]) * mk;
        states[(size_t)row * D_ + d] = y;
        if (dst3) {
            __nv_bfloat16 h = __float2bfloat16(y);
            __nv_bfloat16* drow = dst3 + (size_t)row * 3 * D_;
            drow[d]          = h;
            drow[D_ + d]     = h;
            drow[2 * D_ + d] = __float2bfloat16(y - __bfloat162float(h));
        }
    }
}

// ---------------- per-batch edge-count flag ----------------
__global__ void flag_kernel(const float* __restrict__ mask) {
    const int b = blockIdx.x;
    __shared__ float red[8];
    float s = mask[b * E_ + threadIdx.x];
    s = blockSum256(s, red);
    if (threadIdx.x == 0) g_flag[b] = (s == 0.f) ? 0.f : 1.f;
}

// ---------------- memory-token cross attention (writes mem triple) ----------------
__global__ void attn_kernel(const float* __restrict__ mask) {
    const int b = blockIdx.x / M_, m = blockIdx.x % M_;
    __shared__ float qh[DH_];
    __shared__ float w[E_];
    __shared__ float red[8];
    __shared__ float part[4][DH_];
    const int tid = threadIdx.x;
    const float scale = 0.125f;
    const float mk = mask[b * E_ + tid];
    const int grp = tid >> 6, dd = tid & 63;

    for (int h = 0; h < H_; h++) {
        if (tid < DH_) qh[tid] = g_qbuf[(size_t)m * D_ + h * DH_ + tid];
        __syncthreads();
        const float4* kp4 = reinterpret_cast<const float4*>(
            &g_kbuf[((size_t)(b * E_ + tid)) * D_ + h * DH_]);
        const float4* qh4 = reinterpret_cast<const float4*>(qh);
        float s = 0.f;
        #pragma unroll
        for (int d = 0; d < DH_ / 4; d++) {
            float4 kv = kp4[d], qv = qh4[d];
            s += kv.x * qv.x + kv.y * qv.y + kv.z * qv.z + kv.w * qv.w;
        }
        s *= scale;
        if (mk == 0.f) s = -FLT_MAX;
        float mx = blockMax256(s, red);
        float e  = expf(s - mx);
        float sm = blockSum256(e, red);
        w[tid] = e / sm;
        __syncthreads();
        float acc = 0.f;
        #pragma unroll 4
        for (int e2 = grp * 64; e2 < (grp + 1) * 64; e2++)
            acc += w[e2] * g_vbuf[((size_t)(b * E_ + e2)) * D_ + h * DH_ + dd];
        part[grp][dd] = acc;
        __syncthreads();
        if (tid < DH_) {
            const float a = part[0][tid] + part[1][tid] + part[2][tid] + part[3][tid];
            __nv_bfloat16 hh = __float2bfloat16(a);
            __nv_bfloat16* drow = c_mem + ((size_t)(b * M_ + m)) * 3 * D_ + h * DH_ + tid;
            drow[0]      = hh;
            drow[D_]     = hh;
            drow[2 * D_] = __float2bfloat16(a - __bfloat162float(hh));
        }
        __syncthreads();
    }
}

// ---------------- host side ----------------
static inline void run_cvt3(const float* src, __nv_bfloat16* dst, int K,
                            int rows_src, int rows_tot, int modeW, cudaStream_t st)
{
    size_t n4 = (size_t)rows_tot * K / 4;
    int blocks = (int)((n4 + 255) / 256);
    if (blocks > 2048) blocks = 2048;
    cvt3_kernel<<<blocks, 256, 0, st>>>(src, dst, K, rows_src, rows_tot, modeW);
}

template<int EPI, int OUT>
static inline void run_tmma(const __nv_bfloat16* A, const __nv_bfloat16* W, const float* bias,
                            float* C, __nv_bfloat16* C3, int Mrows, int N, int K3,
                            const float* flag = nullptr, int flagdiv = 1,
                            cudaStream_t st = 0)
{
    cudaFuncSetAttribute(tmma_kernel<EPI, OUT>, cudaFuncAttributeMaxDynamicSharedMemorySize, TM_SMEM);
    dim3 grid(N / 64, Mrows / 128);
    tmma_kernel<EPI, OUT><<<grid, 256, TM_SMEM, st>>>(A, W, bias, C, C3, N, K3, flag, flagdiv);
}

extern "C" void kernel_launch(void* const* d_in, const int* in_sizes, int n_in,
                              void* d_out, int out_size)
{
    const int*   eids  = (const int*)  d_in[0];
    const int*   nids  = (const int*)  d_in[1];
    const float* mask  = (const float*)d_in[2];
    const float* rel   = (const float*)d_in[3];
    const float* rp_w  = (const float*)d_in[4];
    const float* rp_b  = (const float*)d_in[5];
    const float* vw    = (const float*)d_in[6];
    const float* vb    = (const float*)d_in[7];
    const float* ow    = (const float*)d_in[8];
    const float* ob    = (const float*)d_in[9];
    const float* n1g   = (const float*)d_in[10];
    const float* n1b   = (const float*)d_in[11];
    const float* n2g   = (const float*)d_in[12];
    const float* n2b   = (const float*)d_in[13];
    const float* w1    = (const float*)d_in[14];
    const float* b1    = (const float*)d_in[15];
    const float* w2    = (const float*)d_in[16];
    const float* b2    = (const float*)d_in[17];
    const float* memq  = (const float*)d_in[18];
    const float* qw    = (const float*)d_in[19];
    const float* qb    = (const float*)d_in[20];
    const float* kw    = (const float*)d_in[21];
    const float* kb    = (const float*)d_in[22];
    const float* vw2   = (const float*)d_in[23];
    const float* vb2   = (const float*)d_in[24];
    const float* tow   = (const float*)d_in[25];
    const float* tob   = (const float*)d_in[26];
    const float* pw    = (const float*)d_in[27];
    const float* pb    = (const float*)d_in[28];
    float* out = (float*)d_out;

    float *p_proj, *p_states, *p_t2, *p_k, *p_v, *p_q, *p_flag;
    cudaGetSymbolAddress((void**)&p_proj,   g_proj);
    cudaGetSymbolAddress((void**)&p_states, g_states);
    cudaGetSymbolAddress((void**)&p_t2,     g_t2);
    cudaGetSymbolAddress((void**)&p_k,      g_kbuf);
    cudaGetSymbolAddress((void**)&p_v,      g_vbuf);
    cudaGetSymbolAddress((void**)&p_q,      g_qbuf);
    cudaGetSymbolAddress((void**)&p_flag,   g_flag);

    __nv_bfloat16 *x_agg,*x_t1,*x_st,*x_hid,*x_mq,*x_mem,*x_memo;
    __nv_bfloat16 *x_vw,*x_ow,*x_w1,*x_w2,*x_qw,*x_kw,*x_v2,*x_tw,*x_pw;
    cudaGetSymbolAddress((void**)&x_agg,  c_agg);
    cudaGetSymbolAddress((void**)&x_t1,   c_t1);
    cudaGetSymbolAddress((void**)&x_st,   c_st);
    cudaGetSymbolAddress((void**)&x_hid,  c_hid);
    cudaGetSymbolAddress((void**)&x_mq,   c_mq);
    cudaGetSymbolAddress((void**)&x_mem,  c_mem);
    cudaGetSymbolAddress((void**)&x_memo, c_memo);
    cudaGetSymbolAddress((void**)&x_vw,   c_vw);
    cudaGetSymbolAddress((void**)&x_ow,   c_ow);
    cudaGetSymbolAddress((void**)&x_w1,   c_w1);
    cudaGetSymbolAddress((void**)&x_w2,   c_w2);
    cudaGetSymbolAddress((void**)&x_qw,   c_qw);
    cudaGetSymbolAddress((void**)&x_kw,   c_kw);
    cudaGetSymbolAddress((void**)&x_v2,   c_v2);
    cudaGetSymbolAddress((void**)&x_tw,   c_tw);
    cudaGetSymbolAddress((void**)&x_pw,   c_pw);

    // Side stream for weight conversions (capture-legal fork/join)
    static cudaStream_t s2 = nullptr;
    static cudaEvent_t evFork = nullptr, evJoin = nullptr;
    if (!s2) {
        cudaStreamCreateWithFlags(&s2, cudaStreamNonBlocking);
        cudaEventCreateWithFlags(&evFork, cudaEventDisableTiming);
        cudaEventCreateWithFlags(&evJoin, cudaEventDisableTiming);
    }

    cudaEventRecord(evFork, 0);
    cudaStreamWaitEvent(s2, evFork, 0);

    // ---- branch s2: weight triples, mem_q triple, q GEMM, flags ----
    run_cvt3(vw,  x_vw, D_,  L_*D_,  L_*D_,  1, s2);
    run_cvt3(ow,  x_ow, D_,  L_*D_,  L_*D_,  1, s2);
    run_cvt3(w1,  x_w1, D_,  L_*FF_, L_*FF_, 1, s2);
    run_cvt3(w2,  x_w2, FF_, L_*D_,  L_*D_,  1, s2);
    run_cvt3(qw,  x_qw, D_,  D_, D_, 1, s2);
    run_cvt3(kw,  x_kw, D_,  D_, D_, 1, s2);
    run_cvt3(vw2, x_v2, D_,  D_, D_, 1, s2);
    run_cvt3(tow, x_tw, D_,  D_, D_, 1, s2);
    run_cvt3(pw,  x_pw, D_,  HL_, HL_, 1, s2);
    run_cvt3(memq, x_mq, D_, M_, 128, 0, s2);
    run_tmma<0,0>(x_mq, x_qw, qb, p_q, nullptr, 128, D_, 3*D_, nullptr, 1, s2);
    flag_kernel<<<B_, 256, 0, s2>>>(mask);
    cudaEventRecord(evJoin, s2);

    // ---- main chain: exact fp32 proj -> norms -> top-k/agg ----
    {
        dim3 grid(D_ / 64, (R_ + 127) / 128);
        gemm_kernel<<<grid, 256>>>(rel, rp_w, rp_b, p_proj, R_, D_, RD_);
    }
    invnorm_kernel<<<R_, 128>>>();
    sims_kernel<<<BE_, 256>>>(eids, nids);

    cudaStreamWaitEvent((cudaStream_t)0, evJoin, 0);

    // ---- relation-context layers (fused triple epilogues) ----
    for (int l = 0; l < L_; l++) {
        run_tmma<0,1>(x_agg, x_vw + (size_t)l*D_*3*D_, vb + l*D_, nullptr, x_t1, BE_, D_, 3*D_);
        run_tmma<0,0>(x_t1,  x_ow + (size_t)l*D_*3*D_, ob + l*D_, p_t2, nullptr, BE_, D_, 3*D_);
        addln_kernel<<<BE_, 256>>>(p_states, p_t2, n1g + l*D_, n1b + l*D_, mask, 0, x_st);
        run_tmma<1,1>(x_st,  x_w1 + (size_t)l*FF_*3*D_, b1 + l*FF_, nullptr, x_hid, BE_, FF_, 3*D_);
        run_tmma<0,0>(x_hid, x_w2 + (size_t)l*D_*3*FF_, b2 + l*D_, p_t2, nullptr, BE_, D_, 3*FF_);
        addln_kernel<<<BE_, 256>>>(p_states, p_t2, n2g + l*D_, n2b + l*D_, mask, 1,
                                   (l == L_-1) ? x_st : nullptr);
    }

    // ---- tokenizer projections + attention ----
    run_tmma<0,0>(x_st, x_kw, kb,  p_k, nullptr, BE_, D_, 3*D_);
    run_tmma<0,0>(x_st, x_v2, vb2, p_v, nullptr, BE_, D_, 3*D_);
    attn_kernel<<<B_ * M_, 256>>>(mask);

    // ---- memory out-proj (flag) -> final LLM projection ----
    run_tmma<2,1>(x_mem, x_tw, tob, nullptr, x_memo, B_*M_, D_, 3*D_, p_flag, M_);
    run_tmma<0,0>(x_memo, x_pw, pb, out, nullptr, B_*M_, HL_, 3*D_);
}

// round 10
// speedup vs baseline: 2.6065x; 1.1264x over previous
#include <cuda_runtime.h>
#include <cuda_bf16.h>
#include <math.h>
#include <float.h>
#include <stdint.h>

// Problem constants
#define B_   8
#define E_   256
#define N_   32
#define D_   512
#define RD_  768
#define R_   2000
#define L_   2
#define K_   8
#define M_   32
#define H_   8
#define DH_  64
#define HL_  4096
#define BE_  (B_*E_)     // 2048
#define FF_  (4*D_)      // 2048

// ---------------- fp32 scratch ----------------
__device__ float g_proj [R_*D_];
__device__ float g_invn [R_];
__device__ float g_states[BE_*D_];
__device__ float g_t2   [BE_*D_];
__device__ float g_kbuf [BE_*D_];
__device__ float g_vbuf [BE_*D_];
__device__ float g_qbuf [128*D_];
__device__ float g_flag [B_];

// ---------------- bf16 2-slot buffers: X' = [Xhi | Xlo] along K ----------------
__device__ __align__(16) __nv_bfloat16 c_agg [BE_*2*D_];
__device__ __align__(16) __nv_bfloat16 c_t1  [BE_*2*D_];
__device__ __align__(16) __nv_bfloat16 c_st  [BE_*2*D_];
__device__ __align__(16) __nv_bfloat16 c_hid [BE_*2*FF_];
__device__ __align__(16) __nv_bfloat16 c_mq  [128*2*D_];
__device__ __align__(16) __nv_bfloat16 c_mem [256*2*D_];
__device__ __align__(16) __nv_bfloat16 c_memo[256*2*D_];
__device__ __align__(16) __nv_bfloat16 c_vw  [L_*D_*2*D_];
__device__ __align__(16) __nv_bfloat16 c_ow  [L_*D_*2*D_];
__device__ __align__(16) __nv_bfloat16 c_w1  [L_*FF_*2*D_];
__device__ __align__(16) __nv_bfloat16 c_w2  [L_*D_*2*FF_];
__device__ __align__(16) __nv_bfloat16 c_qw  [D_*2*D_];
__device__ __align__(16) __nv_bfloat16 c_kw  [D_*2*D_];
__device__ __align__(16) __nv_bfloat16 c_v2  [D_*2*D_];
__device__ __align__(16) __nv_bfloat16 c_tw  [D_*2*D_];
__device__ __align__(16) __nv_bfloat16 c_pw  [HL_*2*D_];

// ---------------- helpers ----------------
__device__ __forceinline__ uint32_t smem_u32(const void* p) {
    uint32_t a;
    asm("{ .reg .u64 t; cvta.to.shared.u64 t, %1; cvt.u32.u64 %0, t; }" : "=r"(a) : "l"(p));
    return a;
}
#define SWZ(x) ((x) ^ (((x) >> 3) & 0x70))

__device__ __forceinline__ void ldsm4(uint32_t r[4], uint32_t addr) {
    asm volatile("ldmatrix.sync.aligned.m8n8.x4.shared.b16 {%0,%1,%2,%3}, [%4];"
        : "=r"(r[0]), "=r"(r[1]), "=r"(r[2]), "=r"(r[3]) : "r"(addr));
}
__device__ __forceinline__ void mma16816(float c[4], const uint32_t a[4],
                                         uint32_t b0, uint32_t b1) {
    asm volatile("mma.sync.aligned.m16n8k16.row.col.f32.bf16.bf16.f32 "
        "{%0,%1,%2,%3}, {%4,%5,%6,%7}, {%8,%9}, {%0,%1,%2,%3};"
        : "+f"(c[0]), "+f"(c[1]), "+f"(c[2]), "+f"(c[3])
        : "r"(a[0]), "r"(a[1]), "r"(a[2]), "r"(a[3]), "r"(b0), "r"(b1));
}
#define CP_ASYNC16(smaddr, gptr) \
    asm volatile("cp.async.cg.shared.global [%0], [%1], 16;" :: "r"(smaddr), "l"(gptr))
#define CP_COMMIT() asm volatile("cp.async.commit_group;" ::: "memory")
#define CP_WAIT1()  asm volatile("cp.async.wait_group 1;" ::: "memory")
#define CP_WAIT0()  asm volatile("cp.async.wait_group 0;" ::: "memory")

// Stage: Ah 16K | Al 16K | Wh 8K | Wl 8K = 48KB; 2 stages = 96KB -> 2 CTAs/SM
#define STAGE_BYTES 49152
#define AL_OFF 16384
#define WH_OFF 32768
#define WL_OFF 40960
#define TM_SMEM (2*STAGE_BYTES)

__device__ __forceinline__ void split_pair(float v0, float v1,
                                           __nv_bfloat162& hp, __nv_bfloat162& lp) {
    __nv_bfloat16 h0 = __float2bfloat16(v0), h1 = __float2bfloat16(v1);
    hp = __nv_bfloat162(h0, h1);
    lp = __nv_bfloat162(__float2bfloat16(v0 - __bfloat162float(h0)),
                        __float2bfloat16(v1 - __bfloat162float(h1)));
}

// ================= bf16 split GEMM: C = (Ah+Al)(Wh+Wl)^T + bias (3 products) =================
// A',W' stored 2-slot [hi|lo] (row stride 2K). Tile 128x64, 8 warps, 64-K chunks,
// 2-stage cp.async double buffer, cross products formed in-register.
// EPI: 0 none, 1 exact GELU, 2 flag-mul.  OUT: 0 fp32 C, 1 bf16 2-slot C3 [hi|lo]
template<int EPI, int OUT>
__global__ __launch_bounds__(256)
void tmma_kernel(const __nv_bfloat16* __restrict__ A, const __nv_bfloat16* __restrict__ W,
                 const float* __restrict__ bias, float* __restrict__ C,
                 __nv_bfloat16* __restrict__ C3,
                 int N, int Kr, const float* __restrict__ flag, int flagdiv)
{
    extern __shared__ char smem[];
    const uint32_t sbase = smem_u32(smem);
    const int tid = threadIdx.x, wid = tid >> 5, lane = tid & 31;
    const int wm = wid >> 1, wn = wid & 1;
    const int bm = blockIdx.y * 128, bn = blockIdx.x * 64;
    const int K2 = 2 * Kr;
    const int nc = Kr >> 6;

    float acc[2][4][4] = {};

    auto issue_load = [&](int stage, int c) {
        const uint32_t sa = sbase + stage * STAGE_BYTES;
        const size_t hoff = (size_t)c * 64;
        const size_t loff = (size_t)Kr + c * 64;
        #pragma unroll
        for (int i = 0; i < 4; i++) {                  // A hi
            int idx = tid + i * 256;
            int row = idx >> 3, kb = (idx & 7) * 16;
            const char* g = (const char*)(A + (size_t)(bm + row) * K2 + hoff) + kb;
            CP_ASYNC16(sa + SWZ((uint32_t)(row * 128 + kb)), g);
        }
        #pragma unroll
        for (int i = 0; i < 4; i++) {                  // A lo
            int idx = tid + i * 256;
            int row = idx >> 3, kb = (idx & 7) * 16;
            const char* g = (const char*)(A + (size_t)(bm + row) * K2 + loff) + kb;
            CP_ASYNC16(sa + AL_OFF + SWZ((uint32_t)(row * 128 + kb)), g);
        }
        #pragma unroll
        for (int i = 0; i < 2; i++) {                  // W hi
            int idx = tid + i * 256;
            int row = idx >> 3, kb = (idx & 7) * 16;
            const char* g = (const char*)(W + (size_t)(bn + row) * K2 + hoff) + kb;
            CP_ASYNC16(sa + WH_OFF + SWZ((uint32_t)(row * 128 + kb)), g);
        }
        #pragma unroll
        for (int i = 0; i < 2; i++) {                  // W lo
            int idx = tid + i * 256;
            int row = idx >> 3, kb = (idx & 7) * 16;
            const char* g = (const char*)(W + (size_t)(bn + row) * K2 + loff) + kb;
            CP_ASYNC16(sa + WL_OFF + SWZ((uint32_t)(row * 128 + kb)), g);
        }
    };

    issue_load(0, 0); CP_COMMIT();

    for (int c = 0; c < nc; c++) {
        if (c + 1 < nc) {
            issue_load((c + 1) & 1, c + 1); CP_COMMIT();
            CP_WAIT1();
        } else {
            CP_WAIT0();
        }
        __syncthreads();

        const uint32_t sa = sbase + (c & 1) * STAGE_BYTES;
        #pragma unroll
        for (int kk = 0; kk < 4; kk++) {
            uint32_t ah[2][4], al[2][4], bh[2][4], bl[2][4];
            const int kb = kk * 32 + ((lane >> 4) << 4);
            #pragma unroll
            for (int mi = 0; mi < 2; mi++) {
                const uint32_t ra = SWZ((uint32_t)((wm * 32 + mi * 16 + (lane & 15)) * 128 + kb));
                ldsm4(ah[mi], sa + ra);
                ldsm4(al[mi], sa + AL_OFF + ra);
            }
            #pragma unroll
            for (int bi = 0; bi < 2; bi++) {
                const uint32_t rb = SWZ((uint32_t)((wn * 32 + bi * 16 + (lane & 15)) * 128 + kb));
                ldsm4(bh[bi], sa + WH_OFF + rb);
                ldsm4(bl[bi], sa + WL_OFF + rb);
            }
            #pragma unroll
            for (int mi = 0; mi < 2; mi++)
                #pragma unroll
                for (int j = 0; j < 4; j++)
                    mma16816(acc[mi][j], ah[mi], bh[j >> 1][j & 1], bh[j >> 1][2 + (j & 1)]);
            #pragma unroll
            for (int mi = 0; mi < 2; mi++)
                #pragma unroll
                for (int j = 0; j < 4; j++)
                    mma16816(acc[mi][j], ah[mi], bl[j >> 1][j & 1], bl[j >> 1][2 + (j & 1)]);
            #pragma unroll
            for (int mi = 0; mi < 2; mi++)
                #pragma unroll
                for (int j = 0; j < 4; j++)
                    mma16816(acc[mi][j], al[mi], bh[j >> 1][j & 1], bh[j >> 1][2 + (j & 1)]);
        }
        __syncthreads();
    }

    // ---- epilogue ----
    const int r = lane >> 2, cp2 = (lane & 3) * 2;
    #pragma unroll
    for (int mi = 0; mi < 2; mi++) {
        #pragma unroll
        for (int half = 0; half < 2; half++) {
            const int gm = bm + wm * 32 + mi * 16 + half * 8 + r;
            float fl = 1.f;
            if (EPI == 2) fl = flag[gm / flagdiv];
            #pragma unroll
            for (int j = 0; j < 4; j++) {
                const int off = j * 8 + cp2;
                const float2 bv = *(const float2*)(bias + bn + wn * 32 + off);
                float v0 = acc[mi][j][half * 2 + 0] + bv.x;
                float v1 = acc[mi][j][half * 2 + 1] + bv.y;
                if (EPI == 1) {
                    v0 = 0.5f * v0 * (1.f + erff(v0 * 0.70710678118654752440f));
                    v1 = 0.5f * v1 * (1.f + erff(v1 * 0.70710678118654752440f));
                }
                if (EPI == 2) { v0 *= fl; v1 *= fl; }
                if (OUT == 0) {
                    *(float2*)(C + (size_t)gm * N + bn + wn * 32 + off) = make_float2(v0, v1);
                } else {
                    __nv_bfloat162 hp, lp;
                    split_pair(v0, v1, hp, lp);
                    __nv_bfloat16* drow = C3 + (size_t)gm * 2 * N + bn + wn * 32 + off;
                    *(__nv_bfloat162*)(drow)     = hp;
                    *(__nv_bfloat162*)(drow + N) = lp;
                }
            }
        }
    }
}

// ================= fp32 -> 2-slot [hi|lo] bf16 split =================
__global__ void cvt2_kernel(const float* __restrict__ src, __nv_bfloat16* __restrict__ dst,
                            int K, int rows_src, int rows_tot)
{
    const size_t ntot = (size_t)rows_tot * K;
    size_t i = ((size_t)blockIdx.x * blockDim.x + threadIdx.x) * 4;
    const size_t stride = (size_t)gridDim.x * blockDim.x * 4;
    for (; i < ntot; i += stride) {
        const int row = (int)(i / K), k = (int)(i % K);
        float4 x = make_float4(0.f, 0.f, 0.f, 0.f);
        if (row < rows_src) x = *(const float4*)(src + (size_t)row * K + k);
        __nv_bfloat162 hp0, lp0, hp1, lp1;
        split_pair(x.x, x.y, hp0, lp0);
        split_pair(x.z, x.w, hp1, lp1);
        __nv_bfloat16* d0 = dst + (size_t)row * 2 * K + k;
        *(__nv_bfloat162*)(d0)         = hp0; *(__nv_bfloat162*)(d0 + 2)     = hp1;
        *(__nv_bfloat162*)(d0 + K)     = lp0; *(__nv_bfloat162*)(d0 + K + 2) = lp1;
    }
}

// ---------------- reductions ----------------
__device__ __forceinline__ float warpSum(float v) {
    #pragma unroll
    for (int o = 16; o; o >>= 1) v += __shfl_down_sync(0xFFFFFFFFu, v, o);
    return v;
}
__device__ __forceinline__ float warpMax(float v) {
    #pragma unroll
    for (int o = 16; o; o >>= 1) v = fmaxf(v, __shfl_down_sync(0xFFFFFFFFu, v, o));
    return v;
}
__device__ __forceinline__ float blockSum256(float v, float* red) {
    float w = warpSum(v);
    if ((threadIdx.x & 31) == 0) red[threadIdx.x >> 5] = w;
    __syncthreads();
    float s = 0.f;
    #pragma unroll
    for (int i = 0; i < 8; i++) s += red[i];
    __syncthreads();
    return s;
}
__device__ __forceinline__ float blockMax256(float v, float* red) {
    float w = warpMax(v);
    if ((threadIdx.x & 31) == 0) red[threadIdx.x >> 5] = w;
    __syncthreads();
    float s = -FLT_MAX;
    #pragma unroll
    for (int i = 0; i < 8; i++) s = fmaxf(s, red[i]);
    __syncthreads();
    return s;
}

// ================= fp32 SGEMM (ONLY the proj table -> top-k selection safety) =================
__global__ __launch_bounds__(256)
void gemm_kernel(const float* __restrict__ A, const float* __restrict__ W,
                 const float* __restrict__ bias, float* __restrict__ C,
                 int M, int N, int K)
{
    __shared__ float As[2][16][132];
    __shared__ float Bs[2][16][68];
    const int bm = blockIdx.y * 128, bn = blockIdx.x * 64;
    const int tid = threadIdx.x;
    const int tx = tid & 15, ty = tid >> 4;
    const int ar  = tid >> 1;
    const int akc = (tid & 1) * 8;
    const int br  = tid >> 2;
    const int bkc = (tid & 3) * 4;
    const bool aValid = (bm + ar) < M;
    const float* __restrict__ aPtr = A + (size_t)(bm + ar) * K + akc;
    const float* __restrict__ bPtr = W + (size_t)(bn + br) * K + bkc;
    float acc[8][4] = {};
    float4 pa0, pa1, pb;
    if (aValid) {
        pa0 = *reinterpret_cast<const float4*>(aPtr);
        pa1 = *reinterpret_cast<const float4*>(aPtr + 4);
    } else { pa0 = make_float4(0.f,0.f,0.f,0.f); pa1 = pa0; }
    pb = *reinterpret_cast<const float4*>(bPtr);
    As[0][akc+0][ar]=pa0.x; As[0][akc+1][ar]=pa0.y; As[0][akc+2][ar]=pa0.z; As[0][akc+3][ar]=pa0.w;
    As[0][akc+4][ar]=pa1.x; As[0][akc+5][ar]=pa1.y; As[0][akc+6][ar]=pa1.z; As[0][akc+7][ar]=pa1.w;
    Bs[0][bkc+0][br]=pb.x;  Bs[0][bkc+1][br]=pb.y;  Bs[0][bkc+2][br]=pb.z;  Bs[0][bkc+3][br]=pb.w;
    __syncthreads();
    const int ntiles = K >> 4;
    int buf = 0;
    for (int t = 0; t < ntiles; t++) {
        const bool hasNext = (t + 1) < ntiles;
        if (hasNext) {
            const int k0n = (t + 1) << 4;
            if (aValid) {
                pa0 = *reinterpret_cast<const float4*>(aPtr + k0n);
                pa1 = *reinterpret_cast<const float4*>(aPtr + k0n + 4);
            }
            pb = *reinterpret_cast<const float4*>(bPtr + k0n);
        }
        #pragma unroll
        for (int kk = 0; kk < 16; kk++) {
            const float4 a0 = *reinterpret_cast<const float4*>(&As[buf][kk][ty * 4]);
            const float4 a1 = *reinterpret_cast<const float4*>(&As[buf][kk][64 + ty * 4]);
            const float4 b0 = *reinterpret_cast<const float4*>(&Bs[buf][kk][tx * 4]);
            float a[8] = {a0.x, a0.y, a0.z, a0.w, a1.x, a1.y, a1.z, a1.w};
            float b[4] = {b0.x, b0.y, b0.z, b0.w};
            #pragma unroll
            for (int i = 0; i < 8; i++)
                #pragma unroll
                for (int j = 0; j < 4; j++) acc[i][j] += a[i] * b[j];
        }
        if (hasNext) {
            const int nb = buf ^ 1;
            As[nb][akc+0][ar]=pa0.x; As[nb][akc+1][ar]=pa0.y; As[nb][akc+2][ar]=pa0.z; As[nb][akc+3][ar]=pa0.w;
            As[nb][akc+4][ar]=pa1.x; As[nb][akc+5][ar]=pa1.y; As[nb][akc+6][ar]=pa1.z; As[nb][akc+7][ar]=pa1.w;
            Bs[nb][bkc+0][br]=pb.x;  Bs[nb][bkc+1][br]=pb.y;  Bs[nb][bkc+2][br]=pb.z;  Bs[nb][bkc+3][br]=pb.w;
            __syncthreads();
            buf = nb;
        }
    }
    const float4 bv = *reinterpret_cast<const float4*>(&bias[bn + tx * 4]);
    const float bias4[4] = {bv.x, bv.y, bv.z, bv.w};
    #pragma unroll
    for (int i = 0; i < 8; i++) {
        const int gm = bm + ((i < 4) ? (ty * 4 + i) : (64 + ty * 4 + (i - 4)));
        if (gm >= M) continue;
        float4 o;
        o.x = acc[i][0] + bias4[0]; o.y = acc[i][1] + bias4[1];
        o.z = acc[i][2] + bias4[2]; o.w = acc[i][3] + bias4[3];
        *reinterpret_cast<float4*>(&C[(size_t)gm * N + bn + tx * 4]) = o;
    }
}

// ---------------- inverse norm per relation ----------------
__global__ void invnorm_kernel() {
    const int r = blockIdx.x;
    __shared__ float red[4];
    float s = 0.f;
    for (int d = threadIdx.x; d < D_; d += 128) {
        float x = g_proj[(size_t)r * D_ + d];
        s += x * x;
    }
    s = warpSum(s);
    if ((threadIdx.x & 31) == 0) red[threadIdx.x >> 5] = s;
    __syncthreads();
    if (threadIdx.x == 0) {
        float t = red[0] + red[1] + red[2] + red[3];
        g_invn[r] = 1.f / fmaxf(sqrtf(t), 1e-12f);
    }
}

// ---------------- per-edge: sims, top-k, agg(2-slot) + states init ----------------
__global__ void sims_kernel(const int* __restrict__ eids, const int* __restrict__ nids) {
    const int row = blockIdx.x;
    __shared__ float rv[D_];
    __shared__ float sims[N_];
    __shared__ int   nid_s[N_];
    __shared__ int   sel[K_];
    const int eid = eids[row];
    for (int d = threadIdx.x; d < D_; d += 256) rv[d] = g_proj[(size_t)eid * D_ + d];
    if (threadIdx.x < N_) nid_s[threadIdx.x] = nids[(size_t)row * N_ + threadIdx.x];
    __syncthreads();

    const int g = threadIdx.x >> 3, sub = threadIdx.x & 7;
    const int nid = nid_s[g];
    const float* np = &g_proj[(size_t)nid * D_];
    float acc = 0.f;
    for (int d = sub; d < D_; d += 8) acc += np[d] * rv[d];
    acc += __shfl_down_sync(0xFFFFFFFFu, acc, 4, 8);
    acc += __shfl_down_sync(0xFFFFFFFFu, acc, 2, 8);
    acc += __shfl_down_sync(0xFFFFFFFFu, acc, 1, 8);
    if (sub == 0) sims[g] = acc * g_invn[nid] * g_invn[eid];
    __syncthreads();

    if (threadIdx.x == 0) {
        unsigned used = 0;
        for (int k = 0; k < K_; k++) {
            float best = -FLT_MAX; int bi = 0;
            for (int n = 0; n < N_; n++)
                if (!((used >> n) & 1u) && sims[n] > best) { best = sims[n]; bi = n; }
            used |= 1u << bi;
            sel[k] = nid_s[bi];
        }
    }
    __syncthreads();

    __nv_bfloat16* arow = c_agg + (size_t)row * 2 * D_;
    for (int d = threadIdx.x; d < D_; d += 256) {
        float s = 0.f;
        #pragma unroll
        for (int k = 0; k < K_; k++) s += g_proj[(size_t)sel[k] * D_ + d];
        const float a = s * (1.f / K_);
        __nv_bfloat16 h = __float2bfloat16(a);
        arow[d]      = h;
        arow[D_ + d] = __float2bfloat16(a - __bfloat162float(h));
        g_states[(size_t)row * D_ + d] = rv[d];
    }
}

// ---------------- residual add + LayerNorm (+ mask) + optional 2-slot out ----------------
__global__ void addln_kernel(float* __restrict__ states, const float* __restrict__ delta,
                             const float* __restrict__ gam, const float* __restrict__ bet,
                             const float* __restrict__ mask, int useMask,
                             __nv_bfloat16* __restrict__ dst2)
{
    const int row = blockIdx.x;
    __shared__ float xs[D_];
    __shared__ float red[8];
    float s = 0.f;
    #pragma unroll
    for (int i = 0; i < 2; i++) {
        int d = threadIdx.x + i * 256;
        float x = states[(size_t)row * D_ + d] + delta[(size_t)row * D_ + d];
        xs[d] = x; s += x;
    }
    s = blockSum256(s, red);
    const float mu = s * (1.f / D_);
    float v = 0.f;
    #pragma unroll
    for (int i = 0; i < 2; i++) {
        int d = threadIdx.x + i * 256;
        float t = xs[d] - mu; v += t * t;
    }
    v = blockSum256(v, red) * (1.f / D_);
    const float r = rsqrtf(v + 1e-5f);
    const float mk = useMask ? mask[row] : 1.f;
    #pragma unroll
    for (int i = 0; i < 2; i++) {
        int d = threadIdx.x + i * 256;
        const float y = ((xs[d] - mu) * r * gam[d] + bet[d]) * mk;
        states[(size_t)row * D_ + d] = y;
        if (dst2) {
            __nv_bfloat16 h = __float2bfloat16(y);
            __nv_bfloat16* drow = dst2 + (size_t)row * 2 * D_;
            drow[d]      = h;
            drow[D_ + d] = __float2bfloat16(y - __bfloat162float(h));
        }
    }
}

// ---------------- per-batch edge-count flag ----------------
__global__ void flag_kernel(const float* __restrict__ mask) {
    const int b = blockIdx.x;
    __shared__ float red[8];
    float s = mask[b * E_ + threadIdx.x];
    s = blockSum256(s, red);
    if (threadIdx.x == 0) g_flag[b] = (s == 0.f) ? 0.f : 1.f;
}

// ---------------- memory-token cross attention (writes mem 2-slot) ----------------
__global__ void attn_kernel(const float* __restrict__ mask) {
    const int b = blockIdx.x / M_, m = blockIdx.x % M_;
    __shared__ float qh[DH_];
    __shared__ float w[E_];
    __shared__ float red[8];
    __shared__ float part[4][DH_];
    const int tid = threadIdx.x;
    const float scale = 0.125f;
    const float mk = mask[b * E_ + tid];
    const int grp = tid >> 6, dd = tid & 63;

    for (int h = 0; h < H_; h++) {
        if (tid < DH_) qh[tid] = g_qbuf[(size_t)m * D_ + h * DH_ + tid];
        __syncthreads();
        const float4* kp4 = reinterpret_cast<const float4*>(
            &g_kbuf[((size_t)(b * E_ + tid)) * D_ + h * DH_]);
        const float4* qh4 = reinterpret_cast<const float4*>(qh);
        float s = 0.f;
        #pragma unroll
        for (int d = 0; d < DH_ / 4; d++) {
            float4 kv = kp4[d], qv = qh4[d];
            s += kv.x * qv.x + kv.y * qv.y + kv.z * qv.z + kv.w * qv.w;
        }
        s *= scale;
        if (mk == 0.f) s = -FLT_MAX;
        float mx = blockMax256(s, red);
        float e  = expf(s - mx);
        float sm = blockSum256(e, red);
        w[tid] = e / sm;
        __syncthreads();
        float acc = 0.f;
        #pragma unroll 4
        for (int e2 = grp * 64; e2 < (grp + 1) * 64; e2++)
            acc += w[e2] * g_vbuf[((size_t)(b * E_ + e2)) * D_ + h * DH_ + dd];
        part[grp][dd] = acc;
        __syncthreads();
        if (tid < DH_) {
            const float a = part[0][tid] + part[1][tid] + part[2][tid] + part[3][tid];
            __nv_bfloat16 hh = __float2bfloat16(a);
            __nv_bfloat16* drow = c_mem + ((size_t)(b * M_ + m)) * 2 * D_ + h * DH_ + tid;
            drow[0]  = hh;
            drow[D_] = __float2bfloat16(a - __bfloat162float(hh));
        }
        __syncthreads();
    }
}

// ---------------- host side ----------------
static inline void run_cvt2(const float* src, __nv_bfloat16* dst, int K,
                            int rows_src, int rows_tot, cudaStream_t st)
{
    size_t n4 = (size_t)rows_tot * K / 4;
    int blocks = (int)((n4 + 255) / 256);
    if (blocks > 2048) blocks = 2048;
    cvt2_kernel<<<blocks, 256, 0, st>>>(src, dst, K, rows_src, rows_tot);
}

template<int EPI, int OUT>
static inline void run_tmma(const __nv_bfloat16* A, const __nv_bfloat16* W, const float* bias,
                            float* C, __nv_bfloat16* C3, int Mrows, int N, int Kr,
                            const float* flag = nullptr, int flagdiv = 1,
                            cudaStream_t st = 0)
{
    cudaFuncSetAttribute(tmma_kernel<EPI, OUT>, cudaFuncAttributeMaxDynamicSharedMemorySize, TM_SMEM);
    dim3 grid(N / 64, Mrows / 128);
    tmma_kernel<EPI, OUT><<<grid, 256, TM_SMEM, st>>>(A, W, bias, C, C3, N, Kr, flag, flagdiv);
}

extern "C" void kernel_launch(void* const* d_in, const int* in_sizes, int n_in,
                              void* d_out, int out_size)
{
    const int*   eids  = (const int*)  d_in[0];
    const int*   nids  = (const int*)  d_in[1];
    const float* mask  = (const float*)d_in[2];
    const float* rel   = (const float*)d_in[3];
    const float* rp_w  = (const float*)d_in[4];
    const float* rp_b  = (const float*)d_in[5];
    const float* vw    = (const float*)d_in[6];
    const float* vb    = (const float*)d_in[7];
    const float* ow    = (const float*)d_in[8];
    const float* ob    = (const float*)d_in[9];
    const float* n1g   = (const float*)d_in[10];
    const float* n1b   = (const float*)d_in[11];
    const float* n2g   = (const float*)d_in[12];
    const float* n2b   = (const float*)d_in[13];
    const float* w1    = (const float*)d_in[14];
    const float* b1    = (const float*)d_in[15];
    const float* w2    = (const float*)d_in[16];
    const float* b2    = (const float*)d_in[17];
    const float* memq  = (const float*)d_in[18];
    const float* qw    = (const float*)d_in[19];
    const float* qb    = (const float*)d_in[20];
    const float* kw    = (const float*)d_in[21];
    const float* kb    = (const float*)d_in[22];
    const float* vw2   = (const float*)d_in[23];
    const float* vb2   = (const float*)d_in[24];
    const float* tow   = (const float*)d_in[25];
    const float* tob   = (const float*)d_in[26];
    const float* pw    = (const float*)d_in[27];
    const float* pb    = (const float*)d_in[28];
    float* out = (float*)d_out;

    float *p_proj, *p_states, *p_t2, *p_k, *p_v, *p_q, *p_flag;
    cudaGetSymbolAddress((void**)&p_proj,   g_proj);
    cudaGetSymbolAddress((void**)&p_states, g_states);
    cudaGetSymbolAddress((void**)&p_t2,     g_t2);
    cudaGetSymbolAddress((void**)&p_k,      g_kbuf);
    cudaGetSymbolAddress((void**)&p_v,      g_vbuf);
    cudaGetSymbolAddress((void**)&p_q,      g_qbuf);
    cudaGetSymbolAddress((void**)&p_flag,   g_flag);

    __nv_bfloat16 *x_agg,*x_t1,*x_st,*x_hid,*x_mq,*x_mem,*x_memo;
    __nv_bfloat16 *x_vw,*x_ow,*x_w1,*x_w2,*x_qw,*x_kw,*x_v2,*x_tw,*x_pw;
    cudaGetSymbolAddress((void**)&x_agg,  c_agg);
    cudaGetSymbolAddress((void**)&x_t1,   c_t1);
    cudaGetSymbolAddress((void**)&x_st,   c_st);
    cudaGetSymbolAddress((void**)&x_hid,  c_hid);
    cudaGetSymbolAddress((void**)&x_mq,   c_mq);
    cudaGetSymbolAddress((void**)&x_mem,  c_mem);
    cudaGetSymbolAddress((void**)&x_memo, c_memo);
    cudaGetSymbolAddress((void**)&x_vw,   c_vw);
    cudaGetSymbolAddress((void**)&x_ow,   c_ow);
    cudaGetSymbolAddress((void**)&x_w1,   c_w1);
    cudaGetSymbolAddress((void**)&x_w2,   c_w2);
    cudaGetSymbolAddress((void**)&x_qw,   c_qw);
    cudaGetSymbolAddress((void**)&x_kw,   c_kw);
    cudaGetSymbolAddress((void**)&x_v2,   c_v2);
    cudaGetSymbolAddress((void**)&x_tw,   c_tw);
    cudaGetSymbolAddress((void**)&x_pw,   c_pw);

    // Side stream for weight conversions (capture-legal fork/join)
    static cudaStream_t s2 = nullptr;
    static cudaEvent_t evFork = nullptr, evJoin = nullptr;
    if (!s2) {
        cudaStreamCreateWithFlags(&s2, cudaStreamNonBlocking);
        cudaEventCreateWithFlags(&evFork, cudaEventDisableTiming);
        cudaEventCreateWithFlags(&evJoin, cudaEventDisableTiming);
    }

    cudaEventRecord(evFork, 0);
    cudaStreamWaitEvent(s2, evFork, 0);

    // ---- branch s2: weight 2-slot splits, mem_q, q GEMM, flags ----
    run_cvt2(vw,  x_vw, D_,  L_*D_,  L_*D_,  s2);
    run_cvt2(ow,  x_ow, D_,  L_*D_,  L_*D_,  s2);
    run_cvt2(w1,  x_w1, D_,  L_*FF_, L_*FF_, s2);
    run_cvt2(w2,  x_w2, FF_, L_*D_,  L_*D_,  s2);
    run_cvt2(qw,  x_qw, D_,  D_, D_, s2);
    run_cvt2(kw,  x_kw, D_,  D_, D_, s2);
    run_cvt2(vw2, x_v2, D_,  D_, D_, s2);
    run_cvt2(tow, x_tw, D_,  D_, D_, s2);
    run_cvt2(pw,  x_pw, D_,  HL_, HL_, s2);
    run_cvt2(memq, x_mq, D_, M_, 128, s2);
    run_tmma<0,0>(x_mq, x_qw, qb, p_q, nullptr, 128, D_, D_, nullptr, 1, s2);
    flag_kernel<<<B_, 256, 0, s2>>>(mask);
    cudaEventRecord(evJoin, s2);

    // ---- main chain: exact fp32 proj -> norms -> top-k/agg ----
    {
        dim3 grid(D_ / 64, (R_ + 127) / 128);
        gemm_kernel<<<grid, 256>>>(rel, rp_w, rp_b, p_proj, R_, D_, RD_);
    }
    invnorm_kernel<<<R_, 128>>>();
    sims_kernel<<<BE_, 256>>>(eids, nids);

    cudaStreamWaitEvent((cudaStream_t)0, evJoin, 0);

    // ---- relation-context layers (fused 2-slot epilogues) ----
    for (int l = 0; l < L_; l++) {
        run_tmma<0,1>(x_agg, x_vw + (size_t)l*D_*2*D_, vb + l*D_, nullptr, x_t1, BE_, D_, D_);
        run_tmma<0,0>(x_t1,  x_ow + (size_t)l*D_*2*D_, ob + l*D_, p_t2, nullptr, BE_, D_, D_);
        addln_kernel<<<BE_, 256>>>(p_states, p_t2, n1g + l*D_, n1b + l*D_, mask, 0, x_st);
        run_tmma<1,1>(x_st,  x_w1 + (size_t)l*FF_*2*D_, b1 + l*FF_, nullptr, x_hid, BE_, FF_, D_);
        run_tmma<0,0>(x_hid, x_w2 + (size_t)l*D_*2*FF_, b2 + l*D_, p_t2, nullptr, BE_, D_, FF_);
        addln_kernel<<<BE_, 256>>>(p_states, p_t2, n2g + l*D_, n2b + l*D_, mask, 1,
                                   (l == L_-1) ? x_st : nullptr);
    }

    // ---- tokenizer projections + attention ----
    run_tmma<0,0>(x_st, x_kw, kb,  p_k, nullptr, BE_, D_, D_);
    run_tmma<0,0>(x_st, x_v2, vb2, p_v, nullptr, BE_, D_, D_);
    attn_kernel<<<B_ * M_, 256>>>(mask);

    // ---- memory out-proj (flag) -> final LLM projection ----
    run_tmma<2,1>(x_mem, x_tw, tob, nullptr, x_memo, B_*M_, D_, D_, p_flag, M_);
    run_tmma<0,0>(x_memo, x_pw, pb, out, nullptr, B_*M_, HL_, D_);
}